// round 5
// baseline (speedup 1.0000x reference)
#include <cuda_runtime.h>
#include <cstdint>

// AF2dMADEBlock: exact sequential raster sweep.
// Cluster of 2 CTAs per batch (rank0 = mu, rank1 = lv), 512 thr/CTA.
// Pipelined tap-split: past-tap partial dots (taps 0-3, 256/320 of the work)
// for pixel p+1 are computed during phase C of pixel p, overlapping the DSMEM
// exchange wait. Phases A/B only do the center-tap (64/320) + reduction.
// All dot FMAs are packed f32x2 (FFMA2) to halve issue cost.

#define EPS 1e-12f
typedef unsigned long long ull;

__device__ __forceinline__ uint32_t smem_u32(const void* p){
  return (uint32_t)__cvta_generic_to_shared((void*)p);
}
__device__ __forceinline__ float elu_f(float x){
  return x > 0.f ? x : (__expf(x) - 1.f);
}
__device__ __forceinline__ void fma2(ull& acc, ull a, ull b){
  asm("fma.rn.f32x2 %0, %1, %2, %0;" : "+l"(acc) : "l"(a), "l"(b));
}
__device__ __forceinline__ ull pack2(float lo, float hi){
  ull r; asm("mov.b64 %0, {%1, %2};" : "=l"(r) : "f"(lo), "f"(hi)); return r;
}
__device__ __forceinline__ float hsum2x2(ull a, ull b){
  float ax, ay, bx, by;
  asm("mov.b64 {%0, %1}, %2;" : "=f"(ax), "=f"(ay) : "l"(a));
  asm("mov.b64 {%0, %1}, %2;" : "=f"(bx), "=f"(by) : "l"(b));
  return (ax + ay) + (bx + by);
}

__global__ void __cluster_dims__(2,1,1) __launch_bounds__(512,1)
made_flow_kernel(const float* __restrict__ xg,
  const float* __restrict__ mw0, const float* __restrict__ mb0,
  const float* __restrict__ mw1, const float* __restrict__ mb1,
  const float* __restrict__ mw2, const float* __restrict__ mb2,
  const float* __restrict__ mwo, const float* __restrict__ mbo,
  const float* __restrict__ lw0, const float* __restrict__ lb0,
  const float* __restrict__ lw1, const float* __restrict__ lb1,
  const float* __restrict__ lw2, const float* __restrict__ lb2,
  const float* __restrict__ lwo, const float* __restrict__ lbo,
  float* __restrict__ out, int out_n)
{
  // rows 0..63 = pixels, row 64 = zero dummy (OOB taps)
  __shared__ __align__(16) float h0g[65*64];
  __shared__ __align__(16) float h1g[65*64];
  __shared__ __align__(16) float w0s[16*64];   // mask-A w0: [(tap*4+ic)][o]
  __shared__ __align__(16) float y_s[64*4];
  __shared__ __align__(16) float x_s[64*4];
  __shared__ __align__(16) float h2s[64];
  __shared__ float b0s[64], b1s[64], b2s[64];
  __shared__ __align__(16) float wos[256];
  __shared__ float bos[4];
  __shared__ __align__(16) float ownout[2][4];
  __shared__ __align__(16) float recv[2][4];
  __shared__ float ls4[4];
  __shared__ __align__(8) unsigned long long mbar[2];

  const int tid = threadIdx.x;
  uint32_t rank; asm("mov.u32 %0, %%cluster_ctarank;" : "=r"(rank));
  const int batch = blockIdx.x >> 1;

  const float* w0g = rank ? lw0 : mw0;
  const float* b0g = rank ? lb0 : mb0;
  const float* w1g = rank ? lw1 : mw1;
  const float* b1g = rank ? lb1 : mb1;
  const float* w2g = rank ? lw2 : mw2;
  const float* b2g = rank ? lb2 : mb2;
  const float* wog = rank ? lwo : mwo;
  const float* bog = rank ? lbo : mbo;

  if (tid == 0){
    asm volatile("mbarrier.init.shared.b64 [%0], %1;"
                 :: "r"(smem_u32(&mbar[0])), "r"(8u) : "memory");
    asm volatile("mbarrier.init.shared.b64 [%0], %1;"
                 :: "r"(smem_u32(&mbar[1])), "r"(8u) : "memory");
  }

  // ---- Stage small weights/biases/x; zero dummy rows ----
  for (int idx = tid; idx < 1024; idx += 512){
    int r = idx >> 6, oo = idx & 63;
    int t = r >> 2, ic = r & 3;
    int ky = (t == 3) ? 1 : 0;
    int kx = (t == 3) ? 0 : t;
    w0s[idx] = w0g[(oo*4 + ic)*9 + ky*3 + kx];
  }
  if (tid < 64){
    float bv = b0g[tid];
    b0s[tid] = bv; b1s[tid] = b1g[tid]; b2s[tid] = b2g[tid];
    float e = elu_f(bv);          // h0[0]: no valid taps at pixel 0
    h0g[tid] = e;
    h0g[64*64 + tid] = 0.f;       // dummy rows
    h1g[64*64 + tid] = 0.f;
  }
  if (tid < 256) wos[tid] = wog[tid];
  if (tid < 4)   bos[tid] = bog[tid];
  if (tid < 256){
    int pos = tid & 63, c = tid >> 6;
    x_s[pos*4 + c] = xg[batch*256 + tid];
  }

  // ---- Masked mask-B weights, packed f32x2, into registers ----
  // thread (o = tid>>3, j = tid&7): i-th chunk covers k = 4j + 32i + {0..3};
  // i in 0..7 -> taps 0..3 (tap = i>>1, ofs = 4j + (i&1)*32), i in 8..9 -> center.
  const int o = tid >> 3;
  const int j = tid & 7;
  ull w1p[20], w2p[20];
  #pragma unroll
  for (int i = 0; i < 10; i++){
    float t1[4], t2[4];
    #pragma unroll
    for (int m = 0; m < 4; m++){
      int k  = (j << 2) + (i << 5) + m;
      int t  = k >> 6, ic = k & 63;
      int ky = (t >= 3) ? 1 : 0;
      int kx = (t >= 3) ? (t - 3) : t;
      int gi = (o*64 + ic)*9 + ky*3 + kx;
      t1[m] = w1g[gi];
      t2[m] = w2g[gi];
    }
    w1p[2*i]   = pack2(t1[0], t1[1]);
    w1p[2*i+1] = pack2(t1[2], t1[3]);
    w2p[2*i]   = pack2(t2[0], t2[1]);
    w2p[2*i+1] = pack2(t2[2], t2[3]);
  }

  __syncthreads();
  asm volatile("barrier.cluster.arrive.aligned;" ::: "memory");
  asm volatile("barrier.cluster.wait.aligned;"   ::: "memory");

  float lsacc = 0.f;
  // past-tap partials for pixel 0: all taps OOB -> zero
  ull pA0 = 0ull, pA1 = 0ull, pB0 = 0ull, pB1 = 0ull;
  const int joff = j << 2;

  for (int p = 0; p < 64; p++){
    // ---- Phase A: h1[p] = ELU(partial + center-dot + b1) ----
    {
      ull a01 = pA0, a23 = pA1;
      const ull* c0 = (const ull*)&h0g[(p << 6) + joff];
      const ull* c1 = (const ull*)&h0g[(p << 6) + joff + 32];
      ull x0 = c0[0], x1 = c0[1], x2 = c1[0], x3 = c1[1];
      fma2(a01, w1p[16], x0); fma2(a23, w1p[17], x1);
      fma2(a01, w1p[18], x2); fma2(a23, w1p[19], x3);
      float s = hsum2x2(a01, a23);
      s += __shfl_xor_sync(0xffffffffu, s, 4, 8);
      s += __shfl_xor_sync(0xffffffffu, s, 2, 8);
      s += __shfl_xor_sync(0xffffffffu, s, 1, 8);
      if (j == 0) h1g[(p << 6) + o] = elu_f(b1s[o] + s);
    }
    __syncthreads();

    // ---- Phase B: h2[p] = ELU(partial + center-dot + b2) ----
    {
      ull a01 = pB0, a23 = pB1;
      const ull* c0 = (const ull*)&h1g[(p << 6) + joff];
      const ull* c1 = (const ull*)&h1g[(p << 6) + joff + 32];
      ull x0 = c0[0], x1 = c0[1], x2 = c1[0], x3 = c1[1];
      fma2(a01, w2p[16], x0); fma2(a23, w2p[17], x1);
      fma2(a01, w2p[18], x2); fma2(a23, w2p[19], x3);
      float s = hsum2x2(a01, a23);
      s += __shfl_xor_sync(0xffffffffu, s, 4, 8);
      s += __shfl_xor_sync(0xffffffffu, s, 2, 8);
      s += __shfl_xor_sync(0xffffffffu, s, 1, 8);
      if (j == 0) h2s[o] = elu_f(b2s[o] + s);
    }
    __syncthreads();

    // ---- Phase C: out conv + exchange (overlapped with p+1 partials) ----
    const int par = p & 1;
    const uint32_t parity = (uint32_t)((p >> 1) & 1);

    if (tid < 128){
      int oc = tid >> 5, l = tid & 31;
      float pr = fmaf(wos[oc*64 + 32 + l], h2s[32 + l], wos[oc*64 + l] * h2s[l]);
      pr += __shfl_down_sync(0xffffffffu, pr, 16, 32);
      pr += __shfl_down_sync(0xffffffffu, pr,  8, 32);
      pr += __shfl_down_sync(0xffffffffu, pr,  4, 32);
      pr += __shfl_down_sync(0xffffffffu, pr,  2, 32);
      pr += __shfl_down_sync(0xffffffffu, pr,  1, 32);
      if (l == 0){
        float v = bos[oc] + pr;
        if (rank){ v *= 0.5f; lsacc += v; }
        ownout[par][oc] = v;
        uint32_t peer = rank ^ 1u;
        uint32_t lrec = smem_u32(&recv[par][oc]);
        uint32_t rrec, rbar;
        asm volatile("mapa.shared::cluster.u32 %0, %1, %2;"
                     : "=r"(rrec) : "r"(lrec), "r"(peer));
        asm volatile("st.shared::cluster.f32 [%0], %1;"
                     :: "r"(rrec), "f"(v) : "memory");
        uint32_t lbar = smem_u32(&mbar[par]);
        asm volatile("mapa.shared::cluster.u32 %0, %1, %2;"
                     : "=r"(rbar) : "r"(lbar), "r"(peer));
        asm volatile("mbarrier.arrive.release.cluster.shared::cluster.b64 _, [%0];"
                     :: "r"(rbar) : "memory");
        asm volatile("mbarrier.arrive.release.cta.shared::cta.b64 _, [%0];"
                     :: "r"(lbar) : "memory");
      }
    }

    // past-tap partial dots for pixel p+1 (layers 1 and 2), hides exchange wait
    if (p < 63){
      const int pn = p + 1, pyn = pn >> 3, pxn = pn & 7;
      int q[4];
      #pragma unroll
      for (int t = 0; t < 3; t++){
        int qy = pyn - 1, qx = pxn - 1 + t;
        q[t] = ((unsigned)qy < 8u && (unsigned)qx < 8u) ? (qy*8 + qx) : 64;
      }
      q[3] = (pxn != 0) ? (pn - 1) : 64;
      ull A0 = 0ull, A1 = 0ull, B0 = 0ull, B1 = 0ull;
      #pragma unroll
      for (int i = 0; i < 8; i++){
        int ofs = (q[i >> 1] << 6) + joff + ((i & 1) << 5);
        const ull* s0 = (const ull*)&h0g[ofs];
        const ull* s1 = (const ull*)&h1g[ofs];
        ull a0 = s0[0], a1v = s0[1];
        ull b0 = s1[0], b1v = s1[1];
        fma2(A0, w1p[2*i], a0); fma2(A1, w1p[2*i+1], a1v);
        fma2(B0, w2p[2*i], b0); fma2(B1, w2p[2*i+1], b1v);
      }
      pA0 = A0; pA1 = A1; pB0 = B0; pB1 = B1;
    }

    if (tid < 64){
      uint32_t lbar = smem_u32(&mbar[par]);
      uint32_t done;
      do {
        asm volatile("{\n\t.reg .pred p;\n\t"
          "mbarrier.try_wait.parity.acquire.cluster.shared::cta.b64 p, [%1], %2, 0x989680;\n\t"
          "selp.b32 %0, 1, 0, p;\n\t}"
          : "=r"(done) : "r"(lbar), "r"(parity) : "memory");
      } while (!done);

      float4 ov = *(const float4*)&ownout[par][0];
      float4 rv = *(const float4*)&recv[par][0];
      float4 xv = *(const float4*)&x_s[p << 2];
      float mu0 = rank ? rv.x : ov.x, ls0 = rank ? ov.x : rv.x;
      float mu1 = rank ? rv.y : ov.y, ls1 = rank ? ov.y : rv.y;
      float mu2 = rank ? rv.z : ov.z, ls2 = rank ? ov.z : rv.z;
      float mu3 = rank ? rv.w : ov.w, ls3 = rank ? ov.w : rv.w;
      float y0 = __fdividef(xv.x - mu0, __expf(ls0) + EPS);
      float y1 = __fdividef(xv.y - mu1, __expf(ls1) + EPS);
      float y2 = __fdividef(xv.z - mu2, __expf(ls2) + EPS);
      float y3 = __fdividef(xv.w - mu3, __expf(ls3) + EPS);
      if (tid < 4){
        float w = (tid == 0) ? y0 : (tid == 1) ? y1 : (tid == 2) ? y2 : y3;
        y_s[(p << 2) + tid] = w;
      }
      if (p < 63){
        int pn = p + 1, pyn = pn >> 3, pxn = pn & 7;
        float acc = b0s[tid];
        #pragma unroll
        for (int t = 0; t < 3; t++){
          int qy = pyn - 1, qx = pxn - 1 + t;
          if ((unsigned)qy < 8u && (unsigned)qx < 8u){
            float4 yq = *(const float4*)&y_s[(qy*8 + qx) << 2];
            acc = fmaf(w0s[(t*4 + 0)*64 + tid], yq.x, acc);
            acc = fmaf(w0s[(t*4 + 1)*64 + tid], yq.y, acc);
            acc = fmaf(w0s[(t*4 + 2)*64 + tid], yq.z, acc);
            acc = fmaf(w0s[(t*4 + 3)*64 + tid], yq.w, acc);
          }
        }
        if (pxn != 0){
          acc = fmaf(w0s[12*64 + tid], y0, acc);
          acc = fmaf(w0s[13*64 + tid], y1, acc);
          acc = fmaf(w0s[14*64 + tid], y2, acc);
          acc = fmaf(w0s[15*64 + tid], y3, acc);
        }
        h0g[(pn << 6) + tid] = elu_f(acc);
      }
    }
    __syncthreads();
  }

  // ---- Outputs ----
  if (rank == 0){
    for (int idx = tid; idx < 256; idx += 512)
      out[batch*256 + idx] = y_s[((idx & 63) << 2) + (idx >> 6)];
  } else {
    if (tid < 128 && (tid & 31) == 0) ls4[tid >> 5] = lsacc;
    __syncthreads();
    if (tid == 0 && out_n >= 8224)
      out[8192 + batch] = (ls4[0] + ls4[1]) + (ls4[2] + ls4[3]);
  }

  asm volatile("barrier.cluster.arrive.aligned;" ::: "memory");
  asm volatile("barrier.cluster.wait.aligned;"   ::: "memory");
}

extern "C" void kernel_launch(void* const* d_in, const int* in_sizes, int n_in,
                              void* d_out, int out_size) {
  const float* p[17];
  for (int i = 0; i < 17 && i < n_in; i++) p[i] = (const float*)d_in[i];
  made_flow_kernel<<<64, 512>>>(
    p[0],
    p[1], p[2], p[3], p[4], p[5], p[6], p[7], p[8],
    p[9], p[10], p[11], p[12], p[13], p[14], p[15], p[16],
    (float*)d_out, out_size);
}

// round 7
// speedup vs baseline: 1.0536x; 1.0536x over previous
#include <cuda_runtime.h>
#include <cstdint>

// AF2dMADEBlock: exact sequential raster sweep.
// Cluster of 2 CTAs per batch (rank0 = mu, rank1 = lv), 512 thr/CTA.
// Per-pixel mu/lv exchange now goes through the ASYNC PROXY:
//   st.async.shared::cluster.mbarrier::complete_tx::bytes  (no generic
//   cluster-scope release/acquire fences -> no CCTL.IVALL on the path).
// Each CTA's mbar[par] expects 32B (4 mu + 4 lv floats, st.async'd by both
// CTAs' conv leaders to both CTAs). Waiters: try_wait.parity.acquire.CTA.
// Tap-split pipelining + FFMA2 dots as in R5.

#define EPS 1e-12f
typedef unsigned long long ull;

__device__ __forceinline__ uint32_t smem_u32(const void* p){
  return (uint32_t)__cvta_generic_to_shared((void*)p);
}
__device__ __forceinline__ float elu_f(float x){
  return x > 0.f ? x : (__expf(x) - 1.f);
}
__device__ __forceinline__ void fma2(ull& acc, ull a, ull b){
  asm("fma.rn.f32x2 %0, %1, %2, %0;" : "+l"(acc) : "l"(a), "l"(b));
}
__device__ __forceinline__ ull pack2(float lo, float hi){
  ull r; asm("mov.b64 %0, {%1, %2};" : "=l"(r) : "f"(lo), "f"(hi)); return r;
}
__device__ __forceinline__ float hsum2x2(ull a, ull b){
  float ax, ay, bx, by;
  asm("mov.b64 {%0, %1}, %2;" : "=f"(ax), "=f"(ay) : "l"(a));
  asm("mov.b64 {%0, %1}, %2;" : "=f"(bx), "=f"(by) : "l"(b));
  return (ax + ay) + (bx + by);
}

__global__ void __cluster_dims__(2,1,1) __launch_bounds__(512,1)
made_flow_kernel(const float* __restrict__ xg,
  const float* __restrict__ mw0, const float* __restrict__ mb0,
  const float* __restrict__ mw1, const float* __restrict__ mb1,
  const float* __restrict__ mw2, const float* __restrict__ mb2,
  const float* __restrict__ mwo, const float* __restrict__ mbo,
  const float* __restrict__ lw0, const float* __restrict__ lb0,
  const float* __restrict__ lw1, const float* __restrict__ lb1,
  const float* __restrict__ lw2, const float* __restrict__ lb2,
  const float* __restrict__ lwo, const float* __restrict__ lbo,
  float* __restrict__ out, int out_n)
{
  // rows 0..63 = pixels, row 64 = zero dummy (OOB taps)
  __shared__ __align__(16) float h0g[65*64];
  __shared__ __align__(16) float h1g[65*64];
  __shared__ __align__(16) float w0s[16*64];   // mask-A w0: [(tap*4+ic)][o]
  __shared__ __align__(16) float y_s[64*4];
  __shared__ __align__(16) float x_s[64*4];
  __shared__ __align__(16) float h2s[64];
  __shared__ float b0s[64], b1s[64], b2s[64];
  __shared__ __align__(16) float wos[256];
  __shared__ float bos[4];
  __shared__ __align__(16) float recv[2][2][4]; // [net][par][oc], async-proxy written
  __shared__ float ls4[4];
  __shared__ __align__(8) unsigned long long mbar[2];

  const int tid = threadIdx.x;
  uint32_t rank; asm("mov.u32 %0, %%cluster_ctarank;" : "=r"(rank));
  const int batch = blockIdx.x >> 1;

  const float* w0g = rank ? lw0 : mw0;
  const float* b0g = rank ? lb0 : mb0;
  const float* w1g = rank ? lw1 : mw1;
  const float* b1g = rank ? lb1 : mb1;
  const float* w2g = rank ? lw2 : mw2;
  const float* b2g = rank ? lb2 : mb2;
  const float* wog = rank ? lwo : mwo;
  const float* bog = rank ? lbo : mbo;

  if (tid == 0){
    asm volatile("mbarrier.init.shared.b64 [%0], %1;"
                 :: "r"(smem_u32(&mbar[0])), "r"(1u) : "memory");
    asm volatile("mbarrier.init.shared.b64 [%0], %1;"
                 :: "r"(smem_u32(&mbar[1])), "r"(1u) : "memory");
    // arm both parities: each pixel phase expects 32B (8 floats)
    asm volatile("mbarrier.arrive.expect_tx.shared.b64 _, [%0], %1;"
                 :: "r"(smem_u32(&mbar[0])), "r"(32u) : "memory");
    asm volatile("mbarrier.arrive.expect_tx.shared.b64 _, [%0], %1;"
                 :: "r"(smem_u32(&mbar[1])), "r"(32u) : "memory");
  }

  // ---- Stage small weights/biases/x; zero dummy rows ----
  for (int idx = tid; idx < 1024; idx += 512){
    int r = idx >> 6, oo = idx & 63;
    int t = r >> 2, ic = r & 3;
    int ky = (t == 3) ? 1 : 0;
    int kx = (t == 3) ? 0 : t;
    w0s[idx] = w0g[(oo*4 + ic)*9 + ky*3 + kx];
  }
  if (tid < 64){
    float bv = b0g[tid];
    b0s[tid] = bv; b1s[tid] = b1g[tid]; b2s[tid] = b2g[tid];
    float e = elu_f(bv);          // h0[0]: no valid taps at pixel 0
    h0g[tid] = e;
    h0g[64*64 + tid] = 0.f;       // dummy rows
    h1g[64*64 + tid] = 0.f;
  }
  if (tid < 256) wos[tid] = wog[tid];
  if (tid < 4)   bos[tid] = bog[tid];
  if (tid < 256){
    int pos = tid & 63, c = tid >> 6;
    x_s[pos*4 + c] = xg[batch*256 + tid];
  }

  // ---- Masked mask-B weights, packed f32x2, into registers ----
  const int o = tid >> 3;
  const int j = tid & 7;
  ull w1p[20], w2p[20];
  #pragma unroll
  for (int i = 0; i < 10; i++){
    float t1[4], t2[4];
    #pragma unroll
    for (int m = 0; m < 4; m++){
      int k  = (j << 2) + (i << 5) + m;
      int t  = k >> 6, ic = k & 63;
      int ky = (t >= 3) ? 1 : 0;
      int kx = (t >= 3) ? (t - 3) : t;
      int gi = (o*64 + ic)*9 + ky*3 + kx;
      t1[m] = w1g[gi];
      t2[m] = w2g[gi];
    }
    w1p[2*i]   = pack2(t1[0], t1[1]);
    w1p[2*i+1] = pack2(t1[2], t1[3]);
    w2p[2*i]   = pack2(t2[0], t2[1]);
    w2p[2*i+1] = pack2(t2[2], t2[3]);
  }

  __syncthreads();
  // peer's mbarrier init+arm must be visible before any st.async targets it
  asm volatile("barrier.cluster.arrive.aligned;" ::: "memory");
  asm volatile("barrier.cluster.wait.aligned;"   ::: "memory");

  float lsacc = 0.f;
  ull pA0 = 0ull, pA1 = 0ull, pB0 = 0ull, pB1 = 0ull;
  const int joff = j << 2;

  for (int p = 0; p < 64; p++){
    // ---- Phase A: h1[p] = ELU(partial + center-dot + b1) ----
    {
      ull a01 = pA0, a23 = pA1;
      const ull* c0 = (const ull*)&h0g[(p << 6) + joff];
      const ull* c1 = (const ull*)&h0g[(p << 6) + joff + 32];
      ull x0 = c0[0], x1 = c0[1], x2 = c1[0], x3 = c1[1];
      fma2(a01, w1p[16], x0); fma2(a23, w1p[17], x1);
      fma2(a01, w1p[18], x2); fma2(a23, w1p[19], x3);
      float s = hsum2x2(a01, a23);
      s += __shfl_xor_sync(0xffffffffu, s, 4, 8);
      s += __shfl_xor_sync(0xffffffffu, s, 2, 8);
      s += __shfl_xor_sync(0xffffffffu, s, 1, 8);
      if (j == 0) h1g[(p << 6) + o] = elu_f(b1s[o] + s);
    }
    __syncthreads();

    // ---- Phase B: h2[p] = ELU(partial + center-dot + b2) ----
    {
      ull a01 = pB0, a23 = pB1;
      const ull* c0 = (const ull*)&h1g[(p << 6) + joff];
      const ull* c1 = (const ull*)&h1g[(p << 6) + joff + 32];
      ull x0 = c0[0], x1 = c0[1], x2 = c1[0], x3 = c1[1];
      fma2(a01, w2p[16], x0); fma2(a23, w2p[17], x1);
      fma2(a01, w2p[18], x2); fma2(a23, w2p[19], x3);
      float s = hsum2x2(a01, a23);
      s += __shfl_xor_sync(0xffffffffu, s, 4, 8);
      s += __shfl_xor_sync(0xffffffffu, s, 2, 8);
      s += __shfl_xor_sync(0xffffffffu, s, 1, 8);
      if (j == 0) h2s[o] = elu_f(b2s[o] + s);
    }
    __syncthreads();

    // ---- Phase C: out conv + async-proxy exchange + p+1 partials/h0 ----
    const int par = p & 1;
    const uint32_t parity = (uint32_t)((p >> 1) & 1);

    if (tid < 128){
      int oc = tid >> 5, l = tid & 31;
      float pr = fmaf(wos[oc*64 + 32 + l], h2s[32 + l], wos[oc*64 + l] * h2s[l]);
      pr += __shfl_down_sync(0xffffffffu, pr, 16, 32);
      pr += __shfl_down_sync(0xffffffffu, pr,  8, 32);
      pr += __shfl_down_sync(0xffffffffu, pr,  4, 32);
      pr += __shfl_down_sync(0xffffffffu, pr,  2, 32);
      pr += __shfl_down_sync(0xffffffffu, pr,  1, 32);
      if (l == 0){
        float v = bos[oc] + pr;
        if (rank){ v *= 0.5f; lsacc += v; }
        uint32_t val = __float_as_uint(v);
        uint32_t lrec = smem_u32(&recv[rank][par][oc]);
        uint32_t lbar = smem_u32(&mbar[par]);
        uint32_t d0, b0a, d1, b1a;
        asm volatile("mapa.shared::cluster.u32 %0, %1, %2;" : "=r"(d0)  : "r"(lrec), "r"(0u));
        asm volatile("mapa.shared::cluster.u32 %0, %1, %2;" : "=r"(b0a) : "r"(lbar), "r"(0u));
        asm volatile("mapa.shared::cluster.u32 %0, %1, %2;" : "=r"(d1)  : "r"(lrec), "r"(1u));
        asm volatile("mapa.shared::cluster.u32 %0, %1, %2;" : "=r"(b1a) : "r"(lbar), "r"(1u));
        asm volatile("st.async.shared::cluster.mbarrier::complete_tx::bytes.u32 [%0], %1, [%2];"
                     :: "r"(d0), "r"(val), "r"(b0a) : "memory");
        asm volatile("st.async.shared::cluster.mbarrier::complete_tx::bytes.u32 [%0], %1, [%2];"
                     :: "r"(d1), "r"(val), "r"(b1a) : "memory");
      }
    }

    // past-tap partial dots for pixel p+1 (layers 1 and 2): overlaps transit
    if (p < 63){
      const int pn = p + 1, pyn = pn >> 3, pxn = pn & 7;
      int q[4];
      #pragma unroll
      for (int t = 0; t < 3; t++){
        int qy = pyn - 1, qx = pxn - 1 + t;
        q[t] = ((unsigned)qy < 8u && (unsigned)qx < 8u) ? (qy*8 + qx) : 64;
      }
      q[3] = (pxn != 0) ? (pn - 1) : 64;
      ull A0 = 0ull, A1 = 0ull, B0 = 0ull, B1 = 0ull;
      #pragma unroll
      for (int i = 0; i < 8; i++){
        int ofs = (q[i >> 1] << 6) + joff + ((i & 1) << 5);
        const ull* s0 = (const ull*)&h0g[ofs];
        const ull* s1 = (const ull*)&h1g[ofs];
        ull a0 = s0[0], a1v = s0[1];
        ull b0 = s1[0], b1v = s1[1];
        fma2(A0, w1p[2*i], a0); fma2(A1, w1p[2*i+1], a1v);
        fma2(B0, w2p[2*i], b0); fma2(B1, w2p[2*i+1], b1v);
      }
      pA0 = A0; pA1 = A1; pB0 = B0; pB1 = B1;
    }

    if (tid < 64){
      uint32_t lbar = smem_u32(&mbar[par]);
      uint32_t done;
      do {
        asm volatile("{\n\t.reg .pred p;\n\t"
          "mbarrier.try_wait.parity.acquire.cta.shared::cta.b64 p, [%1], %2, 0x989680;\n\t"
          "selp.b32 %0, 1, 0, p;\n\t}"
          : "=r"(done) : "r"(lbar), "r"(parity) : "memory");
      } while (!done);
      if (tid == 0 && p < 62){   // re-arm this barrier for pixel p+2
        asm volatile("mbarrier.arrive.expect_tx.shared.b64 _, [%0], %1;"
                     :: "r"(lbar), "r"(32u) : "memory");
      }

      float4 mu4 = *(const float4*)&recv[0][par][0];
      float4 lv4 = *(const float4*)&recv[1][par][0];
      float4 xv  = *(const float4*)&x_s[p << 2];
      float y0 = __fdividef(xv.x - mu4.x, __expf(lv4.x) + EPS);
      float y1 = __fdividef(xv.y - mu4.y, __expf(lv4.y) + EPS);
      float y2 = __fdividef(xv.z - mu4.z, __expf(lv4.z) + EPS);
      float y3 = __fdividef(xv.w - mu4.w, __expf(lv4.w) + EPS);
      if (tid < 4){
        float w = (tid == 0) ? y0 : (tid == 1) ? y1 : (tid == 2) ? y2 : y3;
        y_s[(p << 2) + tid] = w;
      }
      if (p < 63){
        int pn = p + 1, pyn = pn >> 3, pxn = pn & 7;
        float acc = b0s[tid];
        #pragma unroll
        for (int t = 0; t < 3; t++){
          int qy = pyn - 1, qx = pxn - 1 + t;
          if ((unsigned)qy < 8u && (unsigned)qx < 8u){
            float4 yq = *(const float4*)&y_s[(qy*8 + qx) << 2];
            acc = fmaf(w0s[(t*4 + 0)*64 + tid], yq.x, acc);
            acc = fmaf(w0s[(t*4 + 1)*64 + tid], yq.y, acc);
            acc = fmaf(w0s[(t*4 + 2)*64 + tid], yq.z, acc);
            acc = fmaf(w0s[(t*4 + 3)*64 + tid], yq.w, acc);
          }
        }
        if (pxn != 0){
          acc = fmaf(w0s[12*64 + tid], y0, acc);
          acc = fmaf(w0s[13*64 + tid], y1, acc);
          acc = fmaf(w0s[14*64 + tid], y2, acc);
          acc = fmaf(w0s[15*64 + tid], y3, acc);
        }
        h0g[(pn << 6) + tid] = elu_f(acc);
      }
    }
    __syncthreads();
  }

  // ---- Outputs ----
  if (rank == 0){
    for (int idx = tid; idx < 256; idx += 512)
      out[batch*256 + idx] = y_s[((idx & 63) << 2) + (idx >> 6)];
  } else {
    if (tid < 128 && (tid & 31) == 0) ls4[tid >> 5] = lsacc;
    __syncthreads();
    if (tid == 0 && out_n >= 8224)
      out[8192 + batch] = (ls4[0] + ls4[1]) + (ls4[2] + ls4[3]);
  }

  asm volatile("barrier.cluster.arrive.aligned;" ::: "memory");
  asm volatile("barrier.cluster.wait.aligned;"   ::: "memory");
}

extern "C" void kernel_launch(void* const* d_in, const int* in_sizes, int n_in,
                              void* d_out, int out_size) {
  const float* p[17];
  for (int i = 0; i < 17 && i < n_in; i++) p[i] = (const float*)d_in[i];
  made_flow_kernel<<<64, 512>>>(
    p[0],
    p[1], p[2], p[3], p[4], p[5], p[6], p[7], p[8],
    p[9], p[10], p[11], p[12], p[13], p[14], p[15], p[16],
    (float*)d_out, out_size);
}

// round 10
// speedup vs baseline: 1.3071x; 1.2406x over previous
#include <cuda_runtime.h>
#include <cstdint>

// AF2dMADEBlock: wavefront-parallel raster sweep.
// Schedule t = x + 2y: all 4 past taps of a pixel at wavefront t lie at
// wavefront <= t-1, so the 64-pixel recurrence completes in 22 steps with
// 1..4 pixels per step. Cluster of 2 CTAs per batch (rank0=mu, rank1=lv),
// 512 thr/CTA. Per step: A (layer1, all step pixels), B (layer2),
// C1 (out conv + batched async-proxy exchange + next-wave past-partials + y),
// C2 (h0 of next wave). Masked weights in registers, FFMA2 dots, LDS.128.

#define EPS 1e-12f
typedef unsigned long long ull;

__device__ __forceinline__ uint32_t smem_u32(const void* p){
  return (uint32_t)__cvta_generic_to_shared((void*)p);
}
__device__ __forceinline__ float elu_f(float x){
  return x > 0.f ? x : (__expf(x) - 1.f);
}
__device__ __forceinline__ void fma2(ull& acc, ull a, ull b){
  asm("fma.rn.f32x2 %0, %1, %2, %0;" : "+l"(acc) : "l"(a), "l"(b));
}
__device__ __forceinline__ ull pack2(float lo, float hi){
  ull r; asm("mov.b64 %0, {%1, %2};" : "=l"(r) : "f"(lo), "f"(hi)); return r;
}
__device__ __forceinline__ float hsum1(ull a){
  float x, y;
  asm("mov.b64 {%0, %1}, %2;" : "=f"(x), "=f"(y) : "l"(a));
  return x + y;
}
// wavefront t: pixels (y, x=t-2y), ymin..ymax
__device__ __forceinline__ void wf(int t, int& ymin, int& n){
  ymin = (t <= 7) ? 0 : ((t - 6) >> 1);
  int ymax = t >> 1; if (ymax > 7) ymax = 7;
  n = ymax - ymin + 1;
  if (n < 0) n = 0;
}

__global__ void __cluster_dims__(2,1,1) __launch_bounds__(512,1)
made_flow_kernel(const float* __restrict__ xg,
  const float* __restrict__ mw0, const float* __restrict__ mb0,
  const float* __restrict__ mw1, const float* __restrict__ mb1,
  const float* __restrict__ mw2, const float* __restrict__ mb2,
  const float* __restrict__ mwo, const float* __restrict__ mbo,
  const float* __restrict__ lw0, const float* __restrict__ lb0,
  const float* __restrict__ lw1, const float* __restrict__ lb1,
  const float* __restrict__ lw2, const float* __restrict__ lb2,
  const float* __restrict__ lwo, const float* __restrict__ lbo,
  float* __restrict__ out, int out_n)
{
  // rows 0..63 = pixels, row 64 = zero dummy (OOB taps)
  __shared__ __align__(16) float h0g[65*64];
  __shared__ __align__(16) float h1g[65*64];
  __shared__ __align__(16) float w0s[16*64];    // mask-A w0: [(tap*4+ic)][o]
  __shared__ __align__(16) float y_s[64*4];
  __shared__ __align__(16) float x_s[64*4];
  __shared__ __align__(16) float h2s[4*64];     // [step-pixel][ch]
  __shared__ float b0s[64], b1s[64], b2s[64];
  __shared__ __align__(16) float wos[256];
  __shared__ float bos[4];
  __shared__ __align__(16) float recv[2][2][16]; // [net][par][pix*4+oc]
  __shared__ float ls16[16];
  __shared__ __align__(8) unsigned long long mbar[2];

  const int tid = threadIdx.x;
  uint32_t rank; asm("mov.u32 %0, %%cluster_ctarank;" : "=r"(rank));
  const int batch = blockIdx.x >> 1;

  const float* w0g = rank ? lw0 : mw0;
  const float* b0g = rank ? lb0 : mb0;
  const float* w1g = rank ? lw1 : mw1;
  const float* b1g = rank ? lb1 : mb1;
  const float* w2g = rank ? lw2 : mw2;
  const float* b2g = rank ? lb2 : mb2;
  const float* wog = rank ? lwo : mwo;
  const float* bog = rank ? lbo : mbo;

  if (tid == 0){
    asm volatile("mbarrier.init.shared.b64 [%0], %1;"
                 :: "r"(smem_u32(&mbar[0])), "r"(1u) : "memory");
    asm volatile("mbarrier.init.shared.b64 [%0], %1;"
                 :: "r"(smem_u32(&mbar[1])), "r"(1u) : "memory");
    // arm parities for t=0 (n=1) and t=1 (n=1): 32B each (2 nets x 4 oc x 4B x n)
    asm volatile("mbarrier.arrive.expect_tx.shared.b64 _, [%0], %1;"
                 :: "r"(smem_u32(&mbar[0])), "r"(32u) : "memory");
    asm volatile("mbarrier.arrive.expect_tx.shared.b64 _, [%0], %1;"
                 :: "r"(smem_u32(&mbar[1])), "r"(32u) : "memory");
  }

  // ---- Stage small weights/biases/x; zero dummy rows ----
  for (int idx = tid; idx < 1024; idx += 512){
    int r = idx >> 6, oo = idx & 63;
    int t = r >> 2, ic = r & 3;
    int ky = (t == 3) ? 1 : 0;
    int kx = (t == 3) ? 0 : t;
    w0s[idx] = w0g[(oo*4 + ic)*9 + ky*3 + kx];
  }
  if (tid < 64){
    float bv = b0g[tid];
    b0s[tid] = bv; b1s[tid] = b1g[tid]; b2s[tid] = b2g[tid];
    h0g[tid] = elu_f(bv);        // h0[pixel 0]: no valid past taps
    h0g[64*64 + tid] = 0.f;      // dummy rows
    h1g[64*64 + tid] = 0.f;
  }
  if (tid < 256) wos[tid] = wog[tid];
  if (tid < 4)   bos[tid] = bog[tid];
  if (tid < 16)  ls16[tid] = 0.f;
  if (tid < 256){
    int pos = tid & 63, c = tid >> 6;
    x_s[pos*4 + c] = xg[batch*256 + tid];
  }

  // ---- Masked mask-B weights, packed f32x2, into registers ----
  // thread (o = tid>>3, j = tid&7); chunk i covers k = 4j+32i+{0..3};
  // i in 0..7 -> past taps (tap = i>>1, ofs = 4j + (i&1)*32), i 8..9 -> center.
  const int o = tid >> 3;
  const int j = tid & 7;
  ull w1p[20], w2p[20];
  #pragma unroll
  for (int i = 0; i < 10; i++){
    float t1[4], t2[4];
    #pragma unroll
    for (int m = 0; m < 4; m++){
      int k  = (j << 2) + (i << 5) + m;
      int t  = k >> 6, ic = k & 63;
      int ky = (t >= 3) ? 1 : 0;
      int kx = (t >= 3) ? (t - 3) : t;
      int gi = (o*64 + ic)*9 + ky*3 + kx;
      t1[m] = w1g[gi];
      t2[m] = w2g[gi];
    }
    w1p[2*i]   = pack2(t1[0], t1[1]);
    w1p[2*i+1] = pack2(t1[2], t1[3]);
    w2p[2*i]   = pack2(t2[0], t2[1]);
    w2p[2*i+1] = pack2(t2[2], t2[3]);
  }

  __syncthreads();
  asm volatile("barrier.cluster.arrive.aligned;" ::: "memory");
  asm volatile("barrier.cluster.wait.aligned;"   ::: "memory");

  float lsacc = 0.f;
  ull pA[4] = {0,0,0,0}, pB[4] = {0,0,0,0};   // past partials for wave t's pixels
  const int joff = j << 2;
  const int cw   = tid >> 5;       // conv warp id
  const int cpix = cw >> 2, coc = cw & 3, cl = tid & 31;

  for (int t = 0; t < 22; t++){
    int ymin, n;   wf(t, ymin, n);
    int ymin1, n1; wf(t + 1, ymin1, n1);
    int pl[4], pl1[4];
    #pragma unroll
    for (int k = 0; k < 4; k++){
      int yy = ymin + k;  pl[k]  = (yy << 3) + (t - 2*yy);
      int y1 = ymin1 + k; pl1[k] = (y1 << 3) + (t + 1 - 2*y1);
    }

    // ---- Phase A: h1 for all wave-t pixels ----
    {
      float s[4];
      #pragma unroll
      for (int k = 0; k < 4; k++){
        if (k < n){
          const int base = (pl[k] << 6) + joff;
          ulonglong2 c0 = *(const ulonglong2*)&h0g[base];
          ulonglong2 c1 = *(const ulonglong2*)&h0g[base + 32];
          ull a = pA[k];
          fma2(a, w1p[16], c0.x); fma2(a, w1p[17], c0.y);
          fma2(a, w1p[18], c1.x); fma2(a, w1p[19], c1.y);
          s[k] = hsum1(a);
          pA[k] = 0ull;
        } else s[k] = 0.f;
      }
      #pragma unroll
      for (int k = 0; k < 4; k++) s[k] += __shfl_xor_sync(0xffffffffu, s[k], 4, 8);
      #pragma unroll
      for (int k = 0; k < 4; k++) s[k] += __shfl_xor_sync(0xffffffffu, s[k], 2, 8);
      #pragma unroll
      for (int k = 0; k < 4; k++) s[k] += __shfl_xor_sync(0xffffffffu, s[k], 1, 8);
      if (j == 0){
        #pragma unroll
        for (int k = 0; k < 4; k++)
          if (k < n) h1g[(pl[k] << 6) + o] = elu_f(b1s[o] + s[k]);
      }
    }
    __syncthreads();

    // ---- Phase B: h2 for all wave-t pixels ----
    {
      float s[4];
      #pragma unroll
      for (int k = 0; k < 4; k++){
        if (k < n){
          const int base = (pl[k] << 6) + joff;
          ulonglong2 c0 = *(const ulonglong2*)&h1g[base];
          ulonglong2 c1 = *(const ulonglong2*)&h1g[base + 32];
          ull a = pB[k];
          fma2(a, w2p[16], c0.x); fma2(a, w2p[17], c0.y);
          fma2(a, w2p[18], c1.x); fma2(a, w2p[19], c1.y);
          s[k] = hsum1(a);
          pB[k] = 0ull;
        } else s[k] = 0.f;
      }
      #pragma unroll
      for (int k = 0; k < 4; k++) s[k] += __shfl_xor_sync(0xffffffffu, s[k], 4, 8);
      #pragma unroll
      for (int k = 0; k < 4; k++) s[k] += __shfl_xor_sync(0xffffffffu, s[k], 2, 8);
      #pragma unroll
      for (int k = 0; k < 4; k++) s[k] += __shfl_xor_sync(0xffffffffu, s[k], 1, 8);
      if (j == 0){
        #pragma unroll
        for (int k = 0; k < 4; k++)
          if (k < n) h2s[(k << 6) + o] = elu_f(b2s[o] + s[k]);
      }
    }
    __syncthreads();

    // ---- Phase C1: conv + exchange; next-wave past-partials; y ----
    const int par = t & 1;
    const uint32_t parity = (uint32_t)((t >> 1) & 1);

    if (cpix < n){   // warp (cpix, coc): one output value
      const float* h2p = &h2s[cpix << 6];
      float pr = fmaf(wos[coc*64 + 32 + cl], h2p[32 + cl], wos[coc*64 + cl] * h2p[cl]);
      pr += __shfl_down_sync(0xffffffffu, pr, 16, 32);
      pr += __shfl_down_sync(0xffffffffu, pr,  8, 32);
      pr += __shfl_down_sync(0xffffffffu, pr,  4, 32);
      pr += __shfl_down_sync(0xffffffffu, pr,  2, 32);
      pr += __shfl_down_sync(0xffffffffu, pr,  1, 32);
      if (cl == 0){
        float v = bos[coc] + pr;
        if (rank){ v *= 0.5f; lsacc += v; }
        uint32_t val = __float_as_uint(v);
        uint32_t lrec = smem_u32(&recv[rank][par][(cpix << 2) + coc]);
        uint32_t lbar = smem_u32(&mbar[par]);
        uint32_t d0, b0a, d1, b1a;
        asm volatile("mapa.shared::cluster.u32 %0, %1, %2;" : "=r"(d0)  : "r"(lrec), "r"(0u));
        asm volatile("mapa.shared::cluster.u32 %0, %1, %2;" : "=r"(b0a) : "r"(lbar), "r"(0u));
        asm volatile("mapa.shared::cluster.u32 %0, %1, %2;" : "=r"(d1)  : "r"(lrec), "r"(1u));
        asm volatile("mapa.shared::cluster.u32 %0, %1, %2;" : "=r"(b1a) : "r"(lbar), "r"(1u));
        asm volatile("st.async.shared::cluster.mbarrier::complete_tx::bytes.u32 [%0], %1, [%2];"
                     :: "r"(d0), "r"(val), "r"(b0a) : "memory");
        asm volatile("st.async.shared::cluster.mbarrier::complete_tx::bytes.u32 [%0], %1, [%2];"
                     :: "r"(d1), "r"(val), "r"(b1a) : "memory");
      }
    }

    // past-tap partial dots for wave t+1 (layers 1 & 2), overlaps transit
    #pragma unroll
    for (int k = 0; k < 4; k++){
      if (k < n1){
        const int pp = pl1[k];
        const int pyn = pp >> 3, pxn = pp & 7;
        int qq[4];
        #pragma unroll
        for (int tt = 0; tt < 3; tt++){
          int qy = pyn - 1, qx = pxn - 1 + tt;
          qq[tt] = ((unsigned)qy < 8u && (unsigned)qx < 8u) ? (qy*8 + qx) : 64;
        }
        qq[3] = (pxn != 0) ? (pp - 1) : 64;
        ull A = 0ull, B = 0ull;
        #pragma unroll
        for (int i = 0; i < 8; i++){
          const int ofs = (qq[i >> 1] << 6) + joff + ((i & 1) << 5);
          ulonglong2 u0 = *(const ulonglong2*)&h0g[ofs];
          ulonglong2 u1 = *(const ulonglong2*)&h1g[ofs];
          fma2(A, w1p[2*i],   u0.x); fma2(A, w1p[2*i+1], u0.y);
          fma2(B, w2p[2*i],   u1.x); fma2(B, w2p[2*i+1], u1.y);
        }
        pA[k] = A; pB[k] = B;
      }
    }

    if (tid < 16){
      uint32_t lbar = smem_u32(&mbar[par]);
      uint32_t done;
      do {
        asm volatile("{\n\t.reg .pred p;\n\t"
          "mbarrier.try_wait.parity.acquire.cta.shared::cta.b64 p, [%1], %2, 0x989680;\n\t"
          "selp.b32 %0, 1, 0, p;\n\t}"
          : "=r"(done) : "r"(lbar), "r"(parity) : "memory");
      } while (!done);
      if (tid == 0 && t + 2 < 22){  // re-arm for step t+2
        int ym2, n2; wf(t + 2, ym2, n2);
        asm volatile("mbarrier.arrive.expect_tx.shared.b64 _, [%0], %1;"
                     :: "r"(lbar), "r"((uint32_t)(32*n2)) : "memory");
      }
      const int kp = tid >> 2, c = tid & 3;
      if (kp < n){
        const int p = pl[kp];
        float mu = recv[0][par][(kp << 2) + c];
        float lv = recv[1][par][(kp << 2) + c];
        y_s[(p << 2) + c] = __fdividef(x_s[(p << 2) + c] - mu, __expf(lv) + EPS);
      }
    }
    __syncthreads();

    // ---- Phase C2: h0 for wave t+1 pixels ----
    if (tid < 256){
      const int kp = tid >> 6, ch = tid & 63;
      if (kp < n1){
        const int pp = pl1[kp];
        const int pyn = pp >> 3, pxn = pp & 7;
        float acc = b0s[ch];
        #pragma unroll
        for (int tt = 0; tt < 3; tt++){
          int qy = pyn - 1, qx = pxn - 1 + tt;
          if ((unsigned)qy < 8u && (unsigned)qx < 8u){
            float4 yq = *(const float4*)&y_s[(qy*8 + qx) << 2];
            acc = fmaf(w0s[(tt*4 + 0)*64 + ch], yq.x, acc);
            acc = fmaf(w0s[(tt*4 + 1)*64 + ch], yq.y, acc);
            acc = fmaf(w0s[(tt*4 + 2)*64 + ch], yq.z, acc);
            acc = fmaf(w0s[(tt*4 + 3)*64 + ch], yq.w, acc);
          }
        }
        if (pxn != 0){
          float4 yl = *(const float4*)&y_s[(pp - 1) << 2];
          acc = fmaf(w0s[12*64 + ch], yl.x, acc);
          acc = fmaf(w0s[13*64 + ch], yl.y, acc);
          acc = fmaf(w0s[14*64 + ch], yl.z, acc);
          acc = fmaf(w0s[15*64 + ch], yl.w, acc);
        }
        h0g[(pp << 6) + ch] = elu_f(acc);
      }
    }
    __syncthreads();
  }

  // ---- Outputs ----
  if (rank == 0){
    for (int idx = tid; idx < 256; idx += 512)
      out[batch*256 + idx] = y_s[((idx & 63) << 2) + (idx >> 6)];
  } else {
    if (cl == 0) ls16[cw] = lsacc;
    __syncthreads();
    if (tid == 0 && out_n >= 8224){
      float s = 0.f;
      #pragma unroll
      for (int w = 0; w < 16; w++) s += ls16[w];
      out[8192 + batch] = s;
    }
  }

  asm volatile("barrier.cluster.arrive.aligned;" ::: "memory");
  asm volatile("barrier.cluster.wait.aligned;"   ::: "memory");
}

extern "C" void kernel_launch(void* const* d_in, const int* in_sizes, int n_in,
                              void* d_out, int out_size) {
  const float* p[17];
  for (int i = 0; i < 17 && i < n_in; i++) p[i] = (const float*)d_in[i];
  made_flow_kernel<<<64, 512>>>(
    p[0],
    p[1], p[2], p[3], p[4], p[5], p[6], p[7], p[8],
    p[9], p[10], p[11], p[12], p[13], p[14], p[15], p[16],
    (float*)d_out, out_size);
}

// round 11
// speedup vs baseline: 1.3390x; 1.0244x over previous
#include <cuda_runtime.h>
#include <cstdint>

// AF2dMADEBlock: wavefront-parallel raster sweep (t = x + 2y, 22 steps).
// Cluster of 2 CTAs per batch (rank0=mu, rank1=lv), 512 thr/CTA.
// R11: combined h-layer array (immediate-offset LDS), precomputed wavefront
// index tables in smem (kills per-step index ALU), C2 folded into C1 via a
// named barrier (3 full barriers/step). FFMA2 dots, async-proxy exchange.

#define EPS 1e-12f
#define H1OFF (67*64)      // layer-1 offset inside hg (floats)
typedef unsigned long long ull;

__device__ __forceinline__ uint32_t smem_u32(const void* p){
  return (uint32_t)__cvta_generic_to_shared((void*)p);
}
__device__ __forceinline__ float elu_f(float x){
  return x > 0.f ? x : (__expf(x) - 1.f);
}
__device__ __forceinline__ void fma2(ull& acc, ull a, ull b){
  asm("fma.rn.f32x2 %0, %1, %2, %0;" : "+l"(acc) : "l"(a), "l"(b));
}
__device__ __forceinline__ ull pack2(float lo, float hi){
  ull r; asm("mov.b64 %0, {%1, %2};" : "=l"(r) : "f"(lo), "f"(hi)); return r;
}
__device__ __forceinline__ float hsum1(ull a){
  float x, y;
  asm("mov.b64 {%0, %1}, %2;" : "=f"(x), "=f"(y) : "l"(a));
  return x + y;
}
// wavefront w: pixels (y, x=w-2y), y in [ymin, ymax]
__device__ __forceinline__ void wf(int w, int& ymin, int& n){
  ymin = (w <= 7) ? 0 : ((w - 6) >> 1);
  int ymax = w >> 1; if (ymax > 7) ymax = 7;
  n = ymax - ymin + 1;
  if (n < 0) n = 0;
}

__global__ void __cluster_dims__(2,1,1) __launch_bounds__(512,1)
made_flow_kernel(const float* __restrict__ xg,
  const float* __restrict__ mw0, const float* __restrict__ mb0,
  const float* __restrict__ mw1, const float* __restrict__ mb1,
  const float* __restrict__ mw2, const float* __restrict__ mb2,
  const float* __restrict__ mwo, const float* __restrict__ mbo,
  const float* __restrict__ lw0, const float* __restrict__ lb0,
  const float* __restrict__ lw1, const float* __restrict__ lb1,
  const float* __restrict__ lw2, const float* __restrict__ lb2,
  const float* __restrict__ lwo, const float* __restrict__ lbo,
  float* __restrict__ out, int out_n)
{
  // hg[layer][row][ch]: rows 0..63 pixels, 64 = permanent zero, 65 = scratch
  __shared__ __align__(16) float hg[2*67*64];
  __shared__ __align__(16) float w0s[16*64];    // mask-A w0: [(tap*4+ic)][o]
  __shared__ __align__(16) float y_s[65*4];     // row 64 = zero
  __shared__ __align__(16) float x_s[64*4];
  __shared__ __align__(16) float h2s[4*64];     // [slot][ch]
  __shared__ float b0s[64], b1s[64], b2s[64];
  __shared__ __align__(16) float wos[256];
  __shared__ float bos[4];
  __shared__ __align__(16) float recv[2][2][16]; // [net][par][slot*4+oc]
  __shared__ float ls16[16];
  __shared__ __align__(8) unsigned long long mbar[2];
  __shared__ uchar4 pixT[23];                   // pixel id per (step, slot); 65=invalid
  __shared__ uchar4 tapT[23][4];                // tap ids per (wave, slot); 64=OOB
  __shared__ unsigned char nT[24];

  const int tid = threadIdx.x;
  uint32_t rank; asm("mov.u32 %0, %%cluster_ctarank;" : "=r"(rank));
  const int batch = blockIdx.x >> 1;

  const float* w0g = rank ? lw0 : mw0;
  const float* b0g = rank ? lb0 : mb0;
  const float* w1g = rank ? lw1 : mw1;
  const float* b1g = rank ? lb1 : mb1;
  const float* w2g = rank ? lw2 : mw2;
  const float* b2g = rank ? lb2 : mb2;
  const float* wog = rank ? lwo : mwo;
  const float* bog = rank ? lbo : mbo;

  if (tid == 0){
    asm volatile("mbarrier.init.shared.b64 [%0], %1;"
                 :: "r"(smem_u32(&mbar[0])), "r"(1u) : "memory");
    asm volatile("mbarrier.init.shared.b64 [%0], %1;"
                 :: "r"(smem_u32(&mbar[1])), "r"(1u) : "memory");
    // arm parities for t=0 (n=1) and t=1 (n=1): 32B each
    asm volatile("mbarrier.arrive.expect_tx.shared.b64 _, [%0], %1;"
                 :: "r"(smem_u32(&mbar[0])), "r"(32u) : "memory");
    asm volatile("mbarrier.arrive.expect_tx.shared.b64 _, [%0], %1;"
                 :: "r"(smem_u32(&mbar[1])), "r"(32u) : "memory");
  }

  // ---- Wavefront tables ----
  if (tid < 92){
    int w = tid >> 2, k = tid & 3;
    int ymin, n; wf(w, ymin, n);
    if (k == 0) nT[w] = (unsigned char)n;
    unsigned char pix = 65, tq[4] = {64,64,64,64};
    if (k < n){
      int y = ymin + k, x = w - 2*y;
      pix = (unsigned char)(y*8 + x);
      #pragma unroll
      for (int tt = 0; tt < 3; tt++){
        int qy = y - 1, qx = x - 1 + tt;
        tq[tt] = (qy >= 0 && qx >= 0 && qx < 8) ? (unsigned char)(qy*8 + qx) : 64;
      }
      tq[3] = (x > 0) ? (unsigned char)(pix - 1) : 64;
    }
    ((unsigned char*)&pixT[w])[k] = pix;
    tapT[w][k] = make_uchar4(tq[0], tq[1], tq[2], tq[3]);
  }
  if (tid == 92) nT[23] = 0;

  // ---- Stage small weights/biases/x; zero rows ----
  for (int idx = tid; idx < 1024; idx += 512){
    int r = idx >> 6, oo = idx & 63;
    int t = r >> 2, ic = r & 3;
    int ky = (t == 3) ? 1 : 0;
    int kx = (t == 3) ? 0 : t;
    w0s[idx] = w0g[(oo*4 + ic)*9 + ky*3 + kx];
  }
  if (tid < 64){
    float bv = b0g[tid];
    b0s[tid] = bv; b1s[tid] = b1g[tid]; b2s[tid] = b2g[tid];
    hg[tid] = elu_f(bv);                 // h0[pixel 0]
    hg[64*64 + tid] = 0.f;               // zero rows
    hg[H1OFF + 64*64 + tid] = 0.f;
  }
  if (tid < 256) wos[tid] = wog[tid];
  if (tid < 4){  bos[tid] = bog[tid]; y_s[256 + tid] = 0.f; }
  if (tid < 16)  ls16[tid] = 0.f;
  if (tid < 256){
    int pos = tid & 63, c = tid >> 6;
    x_s[pos*4 + c] = xg[batch*256 + tid];
  }

  // ---- Masked mask-B weights, packed f32x2 ----
  // thread (o, j): tap m half h chunk -> w?p[4m+2h+{0,1}], elems tap*64+4j+32h+{0..3}
  const int o = tid >> 3;
  const int j = tid & 7;
  ull w1p[20], w2p[20];
  #pragma unroll
  for (int i = 0; i < 10; i++){
    float t1[4], t2[4];
    #pragma unroll
    for (int m = 0; m < 4; m++){
      int k  = (j << 2) + (i << 5) + m;
      int t  = k >> 6, ic = k & 63;
      int ky = (t >= 3) ? 1 : 0;
      int kx = (t >= 3) ? (t - 3) : t;
      int gi = (o*64 + ic)*9 + ky*3 + kx;
      t1[m] = w1g[gi];
      t2[m] = w2g[gi];
    }
    w1p[2*i]   = pack2(t1[0], t1[1]);
    w1p[2*i+1] = pack2(t1[2], t1[3]);
    w2p[2*i]   = pack2(t2[0], t2[1]);
    w2p[2*i+1] = pack2(t2[2], t2[3]);
  }

  __syncthreads();
  asm volatile("barrier.cluster.arrive.aligned;" ::: "memory");
  asm volatile("barrier.cluster.wait.aligned;"   ::: "memory");

  float lsacc = 0.f;
  ull pA[4] = {0,0,0,0}, pB[4] = {0,0,0,0};
  const int joff = j << 2;
  const int cw = tid >> 5, cpix = cw >> 2, coc = cw & 3, cl = tid & 31;

  for (int t = 0; t < 22; t++){
    const int n  = nT[t];
    const int n1 = nT[t+1];
    const uchar4 pxv = pixT[t];
    const int pls[4] = {pxv.x, pxv.y, pxv.z, pxv.w};

    // ---- Phase A: h1 for wave-t pixels ----
    {
      float s[4];
      #pragma unroll
      for (int k = 0; k < 4; k++){
        if (k < n){
          const float* cb = &hg[pls[k]*64 + joff];
          ulonglong2 c0 = *(const ulonglong2*)cb;
          ulonglong2 c1 = *(const ulonglong2*)(cb + 32);
          ull a = pA[k];
          fma2(a, w1p[16], c0.x); fma2(a, w1p[17], c0.y);
          fma2(a, w1p[18], c1.x); fma2(a, w1p[19], c1.y);
          s[k] = hsum1(a);
        } else s[k] = 0.f;
      }
      #pragma unroll
      for (int k = 0; k < 4; k++) s[k] += __shfl_xor_sync(0xffffffffu, s[k], 4, 8);
      #pragma unroll
      for (int k = 0; k < 4; k++) s[k] += __shfl_xor_sync(0xffffffffu, s[k], 2, 8);
      #pragma unroll
      for (int k = 0; k < 4; k++) s[k] += __shfl_xor_sync(0xffffffffu, s[k], 1, 8);
      if (j == 0){
        #pragma unroll
        for (int k = 0; k < 4; k++)
          if (k < n) hg[H1OFF + pls[k]*64 + o] = elu_f(b1s[o] + s[k]);
      }
    }
    __syncthreads();

    // ---- Phase B: h2 for wave-t pixels ----
    {
      float s[4];
      #pragma unroll
      for (int k = 0; k < 4; k++){
        if (k < n){
          const float* cb = &hg[H1OFF + pls[k]*64 + joff];
          ulonglong2 c0 = *(const ulonglong2*)cb;
          ulonglong2 c1 = *(const ulonglong2*)(cb + 32);
          ull a = pB[k];
          fma2(a, w2p[16], c0.x); fma2(a, w2p[17], c0.y);
          fma2(a, w2p[18], c1.x); fma2(a, w2p[19], c1.y);
          s[k] = hsum1(a);
        } else s[k] = 0.f;
      }
      #pragma unroll
      for (int k = 0; k < 4; k++) s[k] += __shfl_xor_sync(0xffffffffu, s[k], 4, 8);
      #pragma unroll
      for (int k = 0; k < 4; k++) s[k] += __shfl_xor_sync(0xffffffffu, s[k], 2, 8);
      #pragma unroll
      for (int k = 0; k < 4; k++) s[k] += __shfl_xor_sync(0xffffffffu, s[k], 1, 8);
      if (j == 0){
        #pragma unroll
        for (int k = 0; k < 4; k++)
          if (k < n) h2s[(k << 6) + o] = elu_f(b2s[o] + s[k]);
      }
    }
    __syncthreads();

    // ---- Phase C: conv + exchange | partials(t+1) | wait + y + h0(t+1) ----
    const int par = t & 1;
    const uint32_t parity = (uint32_t)((t >> 1) & 1);

    if (cpix < n){
      const float* h2p = &h2s[cpix << 6];
      float pr = fmaf(wos[coc*64 + 32 + cl], h2p[32 + cl], wos[coc*64 + cl] * h2p[cl]);
      pr += __shfl_down_sync(0xffffffffu, pr, 16, 32);
      pr += __shfl_down_sync(0xffffffffu, pr,  8, 32);
      pr += __shfl_down_sync(0xffffffffu, pr,  4, 32);
      pr += __shfl_down_sync(0xffffffffu, pr,  2, 32);
      pr += __shfl_down_sync(0xffffffffu, pr,  1, 32);
      if (cl == 0){
        float v = bos[coc] + pr;
        if (rank){ v *= 0.5f; lsacc += v; }
        uint32_t val = __float_as_uint(v);
        uint32_t lrec = smem_u32(&recv[rank][par][(cpix << 2) + coc]);
        uint32_t lbar = smem_u32(&mbar[par]);
        uint32_t d0, b0a, d1, b1a;
        asm volatile("mapa.shared::cluster.u32 %0, %1, %2;" : "=r"(d0)  : "r"(lrec), "r"(0u));
        asm volatile("mapa.shared::cluster.u32 %0, %1, %2;" : "=r"(b0a) : "r"(lbar), "r"(0u));
        asm volatile("mapa.shared::cluster.u32 %0, %1, %2;" : "=r"(d1)  : "r"(lrec), "r"(1u));
        asm volatile("mapa.shared::cluster.u32 %0, %1, %2;" : "=r"(b1a) : "r"(lbar), "r"(1u));
        asm volatile("st.async.shared::cluster.mbarrier::complete_tx::bytes.u32 [%0], %1, [%2];"
                     :: "r"(d0), "r"(val), "r"(b0a) : "memory");
        asm volatile("st.async.shared::cluster.mbarrier::complete_tx::bytes.u32 [%0], %1, [%2];"
                     :: "r"(d1), "r"(val), "r"(b1a) : "memory");
      }
    }

    // past-tap partials for wave t+1 (both layers), table-driven addressing
    #pragma unroll
    for (int k = 0; k < 4; k++){
      if (k < n1){
        const uchar4 tq = tapT[t+1][k];
        const int taps[4] = {tq.x, tq.y, tq.z, tq.w};
        ull A = 0ull, B = 0ull;
        #pragma unroll
        for (int m = 0; m < 4; m++){
          const float* bp = &hg[taps[m]*64 + joff];
          ulonglong2 u0 = *(const ulonglong2*)bp;
          ulonglong2 u1 = *(const ulonglong2*)(bp + 32);
          ulonglong2 v0 = *(const ulonglong2*)(bp + H1OFF);
          ulonglong2 v1 = *(const ulonglong2*)(bp + H1OFF + 32);
          fma2(A, w1p[4*m],   u0.x); fma2(A, w1p[4*m+1], u0.y);
          fma2(A, w1p[4*m+2], u1.x); fma2(A, w1p[4*m+3], u1.y);
          fma2(B, w2p[4*m],   v0.x); fma2(B, w2p[4*m+1], v0.y);
          fma2(B, w2p[4*m+2], v1.x); fma2(B, w2p[4*m+3], v1.y);
        }
        pA[k] = A; pB[k] = B;
      }
    }

    if (tid < 256){
      uint32_t lbar = smem_u32(&mbar[par]);
      uint32_t done;
      do {
        asm volatile("{\n\t.reg .pred p;\n\t"
          "mbarrier.try_wait.parity.acquire.cta.shared::cta.b64 p, [%1], %2, 0x989680;\n\t"
          "selp.b32 %0, 1, 0, p;\n\t}"
          : "=r"(done) : "r"(lbar), "r"(parity) : "memory");
      } while (!done);
      if (tid == 0 && t + 2 < 22){
        asm volatile("mbarrier.arrive.expect_tx.shared.b64 _, [%0], %1;"
                     :: "r"(lbar), "r"((uint32_t)(32*nT[t+2])) : "memory");
      }
      if (tid < 16){
        const int kp = tid >> 2, c = tid & 3;
        if (kp < n){
          const int p = pls[kp];
          float mu = recv[0][par][(kp << 2) + c];
          float lv = recv[1][par][(kp << 2) + c];
          y_s[(p << 2) + c] = __fdividef(x_s[(p << 2) + c] - mu, __expf(lv) + EPS);
        }
      }
      asm volatile("bar.sync 1, 256;" ::: "memory");
      // h0 for wave t+1 (invalid slots write scratch row 65, branch-free)
      {
        const int kp = tid >> 6, ch = tid & 63;
        const uchar4 tq = tapT[t+1][kp];
        const int wp = ((const unsigned char*)&pixT[t+1])[kp];
        const int taps[4] = {tq.x, tq.y, tq.z, tq.w};
        float acc = b0s[ch];
        #pragma unroll
        for (int tt = 0; tt < 4; tt++){
          float4 yq = *(const float4*)&y_s[taps[tt] << 2];
          acc = fmaf(w0s[(tt*4 + 0)*64 + ch], yq.x, acc);
          acc = fmaf(w0s[(tt*4 + 1)*64 + ch], yq.y, acc);
          acc = fmaf(w0s[(tt*4 + 2)*64 + ch], yq.z, acc);
          acc = fmaf(w0s[(tt*4 + 3)*64 + ch], yq.w, acc);
        }
        hg[wp*64 + ch] = elu_f(acc);
      }
    }
    __syncthreads();
  }

  // ---- Outputs ----
  if (rank == 0){
    for (int idx = tid; idx < 256; idx += 512)
      out[batch*256 + idx] = y_s[((idx & 63) << 2) + (idx >> 6)];
  } else {
    if (cl == 0) ls16[cw] = lsacc;
    __syncthreads();
    if (tid == 0 && out_n >= 8224){
      float s = 0.f;
      #pragma unroll
      for (int w = 0; w < 16; w++) s += ls16[w];
      out[8192 + batch] = s;
    }
  }

  asm volatile("barrier.cluster.arrive.aligned;" ::: "memory");
  asm volatile("barrier.cluster.wait.aligned;"   ::: "memory");
}

extern "C" void kernel_launch(void* const* d_in, const int* in_sizes, int n_in,
                              void* d_out, int out_size) {
  const float* p[17];
  for (int i = 0; i < 17 && i < n_in; i++) p[i] = (const float*)d_in[i];
  made_flow_kernel<<<64, 512>>>(
    p[0],
    p[1], p[2], p[3], p[4], p[5], p[6], p[7], p[8],
    p[9], p[10], p[11], p[12], p[13], p[14], p[15], p[16],
    (float*)d_out, out_size);
}

// round 14
// speedup vs baseline: 1.4039x; 1.0485x over previous
#include <cuda_runtime.h>
#include <cstdint>

// AF2dMADEBlock: wavefront-parallel raster sweep (t = x + 2y, 22 steps).
// Cluster of 2 CTAs per batch (rank0=mu, rank1=lv), 512 thr/CTA.
// R14: shfl_xor reductions (redux.f32 unsupported on sm_103), conv as 8-lane
// groups (shorter send chain, padded smem strides), h0 taps 0-1 hoisted ahead
// of the exchange wait (taps 2-3 are wave-t and must stay post-wait).

#define EPS 1e-12f
#define H1OFF (67*64)      // layer-1 offset inside hg (floats)
typedef unsigned long long ull;

__device__ __forceinline__ uint32_t smem_u32(const void* p){
  return (uint32_t)__cvta_generic_to_shared((void*)p);
}
__device__ __forceinline__ float elu_f(float x){
  return x > 0.f ? x : (__expf(x) - 1.f);
}
__device__ __forceinline__ void fma2(ull& acc, ull a, ull b){
  asm("fma.rn.f32x2 %0, %1, %2, %0;" : "+l"(acc) : "l"(a), "l"(b));
}
__device__ __forceinline__ ull pack2(float lo, float hi){
  ull r; asm("mov.b64 %0, {%1, %2};" : "=l"(r) : "f"(lo), "f"(hi)); return r;
}
__device__ __forceinline__ float hsum1(ull a){
  float x, y;
  asm("mov.b64 {%0, %1}, %2;" : "=f"(x), "=f"(y) : "l"(a));
  return x + y;
}
// wavefront w: pixels (y, x=w-2y), y in [ymin, ymax]
__device__ __forceinline__ void wf(int w, int& ymin, int& n){
  ymin = (w <= 7) ? 0 : ((w - 6) >> 1);
  int ymax = w >> 1; if (ymax > 7) ymax = 7;
  n = ymax - ymin + 1;
  if (n < 0) n = 0;
}

__global__ void __cluster_dims__(2,1,1) __launch_bounds__(512,1)
made_flow_kernel(const float* __restrict__ xg,
  const float* __restrict__ mw0, const float* __restrict__ mb0,
  const float* __restrict__ mw1, const float* __restrict__ mb1,
  const float* __restrict__ mw2, const float* __restrict__ mb2,
  const float* __restrict__ mwo, const float* __restrict__ mbo,
  const float* __restrict__ lw0, const float* __restrict__ lb0,
  const float* __restrict__ lw1, const float* __restrict__ lb1,
  const float* __restrict__ lw2, const float* __restrict__ lb2,
  const float* __restrict__ lwo, const float* __restrict__ lbo,
  float* __restrict__ out, int out_n)
{
  // hg[layer][row][ch]: rows 0..63 pixels, 64 = permanent zero, 65 = scratch
  __shared__ __align__(16) float hg[2*67*64];
  __shared__ __align__(16) float w0s[16*64];    // mask-A w0: [(tap*4+ic)][o]
  __shared__ __align__(16) float y_s[65*4];     // row 64 = zero
  __shared__ __align__(16) float x_s[64*4];
  __shared__ __align__(16) float h2s[4*68];     // [slot][ch], stride 68
  __shared__ float b0s[64], b1s[64], b2s[64];
  __shared__ __align__(16) float wos[4*68];     // [oc][c], stride 68
  __shared__ float bos[4];
  __shared__ __align__(16) float recv[2][2][16]; // [net][par][slot*4+oc]
  __shared__ float ls16[16];
  __shared__ __align__(8) unsigned long long mbar[2];
  __shared__ uchar4 pixT[23];                   // pixel id per (step, slot); 65=invalid
  __shared__ uchar4 tapT[23][4];                // tap ids per (wave, slot); 64=OOB
  __shared__ unsigned char nT[24];

  const int tid = threadIdx.x;
  uint32_t rank; asm("mov.u32 %0, %%cluster_ctarank;" : "=r"(rank));
  const int batch = blockIdx.x >> 1;

  const float* w0g = rank ? lw0 : mw0;
  const float* b0g = rank ? lb0 : mb0;
  const float* w1g = rank ? lw1 : mw1;
  const float* b1g = rank ? lb1 : mb1;
  const float* w2g = rank ? lw2 : mw2;
  const float* b2g = rank ? lb2 : mb2;
  const float* wog = rank ? lwo : mwo;
  const float* bog = rank ? lbo : mbo;

  if (tid == 0){
    asm volatile("mbarrier.init.shared.b64 [%0], %1;"
                 :: "r"(smem_u32(&mbar[0])), "r"(1u) : "memory");
    asm volatile("mbarrier.init.shared.b64 [%0], %1;"
                 :: "r"(smem_u32(&mbar[1])), "r"(1u) : "memory");
    asm volatile("mbarrier.arrive.expect_tx.shared.b64 _, [%0], %1;"
                 :: "r"(smem_u32(&mbar[0])), "r"(32u) : "memory");
    asm volatile("mbarrier.arrive.expect_tx.shared.b64 _, [%0], %1;"
                 :: "r"(smem_u32(&mbar[1])), "r"(32u) : "memory");
  }

  // ---- Wavefront tables ----
  if (tid < 92){
    int w = tid >> 2, k = tid & 3;
    int ymin, n; wf(w, ymin, n);
    if (k == 0) nT[w] = (unsigned char)n;
    unsigned char pix = 65, tq[4] = {64,64,64,64};
    if (k < n){
      int y = ymin + k, x = w - 2*y;
      pix = (unsigned char)(y*8 + x);
      #pragma unroll
      for (int tt = 0; tt < 3; tt++){
        int qy = y - 1, qx = x - 1 + tt;
        tq[tt] = (qy >= 0 && qx >= 0 && qx < 8) ? (unsigned char)(qy*8 + qx) : 64;
      }
      tq[3] = (x > 0) ? (unsigned char)(pix - 1) : 64;
    }
    ((unsigned char*)&pixT[w])[k] = pix;
    tapT[w][k] = make_uchar4(tq[0], tq[1], tq[2], tq[3]);
  }
  if (tid == 92) nT[23] = 0;

  // ---- Stage small weights/biases/x; zero rows ----
  for (int idx = tid; idx < 1024; idx += 512){
    int r = idx >> 6, oo = idx & 63;
    int t = r >> 2, ic = r & 3;
    int ky = (t == 3) ? 1 : 0;
    int kx = (t == 3) ? 0 : t;
    w0s[idx] = w0g[(oo*4 + ic)*9 + ky*3 + kx];
  }
  if (tid < 64){
    float bv = b0g[tid];
    b0s[tid] = bv; b1s[tid] = b1g[tid]; b2s[tid] = b2g[tid];
    hg[tid] = elu_f(bv);                 // h0[pixel 0]
    hg[64*64 + tid] = 0.f;               // zero rows
    hg[H1OFF + 64*64 + tid] = 0.f;
  }
  if (tid < 256) wos[(tid >> 6)*68 + (tid & 63)] = wog[tid];
  if (tid < 4){  bos[tid] = bog[tid]; y_s[256 + tid] = 0.f; }
  if (tid < 16)  ls16[tid] = 0.f;
  if (tid < 256){
    int pos = tid & 63, c = tid >> 6;
    x_s[pos*4 + c] = xg[batch*256 + tid];
  }

  // ---- Masked mask-B weights, packed f32x2 ----
  const int o = tid >> 3;
  const int j = tid & 7;
  ull w1p[20], w2p[20];
  #pragma unroll
  for (int i = 0; i < 10; i++){
    float t1[4], t2[4];
    #pragma unroll
    for (int m = 0; m < 4; m++){
      int k  = (j << 2) + (i << 5) + m;
      int t  = k >> 6, ic = k & 63;
      int ky = (t >= 3) ? 1 : 0;
      int kx = (t >= 3) ? (t - 3) : t;
      int gi = (o*64 + ic)*9 + ky*3 + kx;
      t1[m] = w1g[gi];
      t2[m] = w2g[gi];
    }
    w1p[2*i]   = pack2(t1[0], t1[1]);
    w1p[2*i+1] = pack2(t1[2], t1[3]);
    w2p[2*i]   = pack2(t2[0], t2[1]);
    w2p[2*i+1] = pack2(t2[2], t2[3]);
  }

  __syncthreads();
  asm volatile("barrier.cluster.arrive.aligned;" ::: "memory");
  asm volatile("barrier.cluster.wait.aligned;"   ::: "memory");

  float lsacc = 0.f;
  ull pA[4] = {0,0,0,0}, pB[4] = {0,0,0,0};
  float h0up = 0.f;                      // hoisted h0 partial (taps 0-1 only)
  const int joff = j << 2;

  for (int t = 0; t < 22; t++){
    const int n  = nT[t];
    const int n1 = nT[t+1];
    const uchar4 pxv = pixT[t];
    const int pls[4] = {pxv.x, pxv.y, pxv.z, pxv.w};

    // ---- Phase A: h1 for wave-t pixels ----
    {
      float s[4];
      #pragma unroll
      for (int k = 0; k < 4; k++){
        if (k < n){
          const float* cb = &hg[pls[k]*64 + joff];
          ulonglong2 c0 = *(const ulonglong2*)cb;
          ulonglong2 c1 = *(const ulonglong2*)(cb + 32);
          ull a = pA[k];
          fma2(a, w1p[16], c0.x); fma2(a, w1p[17], c0.y);
          fma2(a, w1p[18], c1.x); fma2(a, w1p[19], c1.y);
          s[k] = hsum1(a);
        } else s[k] = 0.f;
      }
      #pragma unroll
      for (int k = 0; k < 4; k++) s[k] += __shfl_xor_sync(0xffffffffu, s[k], 4, 8);
      #pragma unroll
      for (int k = 0; k < 4; k++) s[k] += __shfl_xor_sync(0xffffffffu, s[k], 2, 8);
      #pragma unroll
      for (int k = 0; k < 4; k++) s[k] += __shfl_xor_sync(0xffffffffu, s[k], 1, 8);
      if (j == 0){
        #pragma unroll
        for (int k = 0; k < 4; k++)
          if (k < n) hg[H1OFF + pls[k]*64 + o] = elu_f(b1s[o] + s[k]);
      }
    }
    __syncthreads();

    // ---- Phase B: h2 for wave-t pixels ----
    {
      float s[4];
      #pragma unroll
      for (int k = 0; k < 4; k++){
        if (k < n){
          const float* cb = &hg[H1OFF + pls[k]*64 + joff];
          ulonglong2 c0 = *(const ulonglong2*)cb;
          ulonglong2 c1 = *(const ulonglong2*)(cb + 32);
          ull a = pB[k];
          fma2(a, w2p[16], c0.x); fma2(a, w2p[17], c0.y);
          fma2(a, w2p[18], c1.x); fma2(a, w2p[19], c1.y);
          s[k] = hsum1(a);
        } else s[k] = 0.f;
      }
      #pragma unroll
      for (int k = 0; k < 4; k++) s[k] += __shfl_xor_sync(0xffffffffu, s[k], 4, 8);
      #pragma unroll
      for (int k = 0; k < 4; k++) s[k] += __shfl_xor_sync(0xffffffffu, s[k], 2, 8);
      #pragma unroll
      for (int k = 0; k < 4; k++) s[k] += __shfl_xor_sync(0xffffffffu, s[k], 1, 8);
      if (j == 0){
        #pragma unroll
        for (int k = 0; k < 4; k++)
          if (k < n) h2s[k*68 + o] = elu_f(b2s[o] + s[k]);
      }
    }
    __syncthreads();

    // ---- Phase C: conv+send | overlap: partials(t+1)+h0 taps0-1 | wait+y+h0 ----
    const int par = t & 1;
    const uint32_t parity = (uint32_t)((t >> 1) & 1);

    // conv: warp w = slot kp (w<n), four 8-lane groups = oc 0..3
    if (tid < 128){
      const int kp = tid >> 5;             // warp id = slot
      const int oc = (tid >> 3) & 3;       // 8-lane group within warp
      const int j8 = tid & 7;
      if (kp < n){
        const ulonglong2* hp = (const ulonglong2*)&h2s[kp*68 + j8*8];
        const ulonglong2* wp = (const ulonglong2*)&wos[oc*68 + j8*8];
        ulonglong2 hv0 = hp[0], hv1 = hp[1];
        ulonglong2 wv0 = wp[0], wv1 = wp[1];
        ull a0 = 0ull, a1 = 0ull;
        fma2(a0, wv0.x, hv0.x); fma2(a1, wv0.y, hv0.y);
        fma2(a0, wv1.x, hv1.x); fma2(a1, wv1.y, hv1.y);
        float pr = hsum1(a0) + hsum1(a1);
        pr += __shfl_xor_sync(0xffffffffu, pr, 4, 8);
        pr += __shfl_xor_sync(0xffffffffu, pr, 2, 8);
        pr += __shfl_xor_sync(0xffffffffu, pr, 1, 8);
        if (j8 == 0){
          float v = bos[oc] + pr;
          if (rank){ v *= 0.5f; lsacc += v; }
          uint32_t val = __float_as_uint(v);
          uint32_t lrec = smem_u32(&recv[rank][par][(kp << 2) + oc]);
          uint32_t lbar = smem_u32(&mbar[par]);
          uint32_t d0, b0a, d1, b1a;
          asm volatile("mapa.shared::cluster.u32 %0, %1, %2;" : "=r"(d0)  : "r"(lrec), "r"(0u));
          asm volatile("mapa.shared::cluster.u32 %0, %1, %2;" : "=r"(b0a) : "r"(lbar), "r"(0u));
          asm volatile("mapa.shared::cluster.u32 %0, %1, %2;" : "=r"(d1)  : "r"(lrec), "r"(1u));
          asm volatile("mapa.shared::cluster.u32 %0, %1, %2;" : "=r"(b1a) : "r"(lbar), "r"(1u));
          asm volatile("st.async.shared::cluster.mbarrier::complete_tx::bytes.u32 [%0], %1, [%2];"
                       :: "r"(d0), "r"(val), "r"(b0a) : "memory");
          asm volatile("st.async.shared::cluster.mbarrier::complete_tx::bytes.u32 [%0], %1, [%2];"
                       :: "r"(d1), "r"(val), "r"(b1a) : "memory");
        }
      }
    }

    // past-tap partials for wave t+1 (both layers), table-driven
    #pragma unroll
    for (int k = 0; k < 4; k++){
      if (k < n1){
        const uchar4 tq = tapT[t+1][k];
        const int taps[4] = {tq.x, tq.y, tq.z, tq.w};
        ull A = 0ull, B = 0ull;
        #pragma unroll
        for (int m = 0; m < 4; m++){
          const float* bp = &hg[taps[m]*64 + joff];
          ulonglong2 u0 = *(const ulonglong2*)bp;
          ulonglong2 u1 = *(const ulonglong2*)(bp + 32);
          ulonglong2 v0 = *(const ulonglong2*)(bp + H1OFF);
          ulonglong2 v1 = *(const ulonglong2*)(bp + H1OFF + 32);
          fma2(A, w1p[4*m],   u0.x); fma2(A, w1p[4*m+1], u0.y);
          fma2(A, w1p[4*m+2], u1.x); fma2(A, w1p[4*m+3], u1.y);
          fma2(B, w2p[4*m],   v0.x); fma2(B, w2p[4*m+1], v0.y);
          fma2(B, w2p[4*m+2], v1.x); fma2(B, w2p[4*m+3], v1.y);
        }
        pA[k] = A; pB[k] = B;
      }
    }

    if (tid < 256){
      // h0 partial for wave t+1: taps 0 (wave t-2) and 1 (wave t-1) are final
      {
        const int kp = tid >> 6, ch = tid & 63;
        const uchar4 tq = tapT[t+1][kp];
        float acc = b0s[ch];
        float4 yq0 = *(const float4*)&y_s[tq.x << 2];
        float4 yq1 = *(const float4*)&y_s[tq.y << 2];
        acc = fmaf(w0s[0*64 + ch], yq0.x, acc);
        acc = fmaf(w0s[1*64 + ch], yq0.y, acc);
        acc = fmaf(w0s[2*64 + ch], yq0.z, acc);
        acc = fmaf(w0s[3*64 + ch], yq0.w, acc);
        acc = fmaf(w0s[4*64 + ch], yq1.x, acc);
        acc = fmaf(w0s[5*64 + ch], yq1.y, acc);
        acc = fmaf(w0s[6*64 + ch], yq1.z, acc);
        acc = fmaf(w0s[7*64 + ch], yq1.w, acc);
        h0up = acc;
      }

      uint32_t lbar = smem_u32(&mbar[par]);
      uint32_t done;
      do {
        asm volatile("{\n\t.reg .pred p;\n\t"
          "mbarrier.try_wait.parity.acquire.cta.shared::cta.b64 p, [%1], %2, 0x989680;\n\t"
          "selp.b32 %0, 1, 0, p;\n\t}"
          : "=r"(done) : "r"(lbar), "r"(parity) : "memory");
      } while (!done);
      if (tid < 16){
        const int kp = tid >> 2, c = tid & 3;
        if (kp < n){
          const int p = pls[kp];
          float mu = recv[0][par][(kp << 2) + c];
          float lv = recv[1][par][(kp << 2) + c];
          y_s[(p << 2) + c] = __fdividef(x_s[(p << 2) + c] - mu, __expf(lv) + EPS);
        }
      }
      if (tid == 0 && t + 2 < 22){
        asm volatile("mbarrier.arrive.expect_tx.shared.b64 _, [%0], %1;"
                     :: "r"(lbar), "r"((uint32_t)(32*nT[t+2])) : "memory");
      }
      asm volatile("bar.sync 1, 256;" ::: "memory");
      // h0 tail: taps 2 (up-right, wave t) and 3 (left, wave t) + ELU + store
      {
        const int kp = tid >> 6, ch = tid & 63;
        const uchar4 tq = tapT[t+1][kp];
        const int wp = ((const unsigned char*)&pixT[t+1])[kp];
        float acc = h0up;
        float4 y2 = *(const float4*)&y_s[tq.z << 2];
        float4 y3 = *(const float4*)&y_s[tq.w << 2];
        acc = fmaf(w0s[ 8*64 + ch], y2.x, acc);
        acc = fmaf(w0s[ 9*64 + ch], y2.y, acc);
        acc = fmaf(w0s[10*64 + ch], y2.z, acc);
        acc = fmaf(w0s[11*64 + ch], y2.w, acc);
        acc = fmaf(w0s[12*64 + ch], y3.x, acc);
        acc = fmaf(w0s[13*64 + ch], y3.y, acc);
        acc = fmaf(w0s[14*64 + ch], y3.z, acc);
        acc = fmaf(w0s[15*64 + ch], y3.w, acc);
        hg[wp*64 + ch] = elu_f(acc);
      }
    }
    __syncthreads();
  }

  // ---- Outputs ----
  if (rank == 0){
    for (int idx = tid; idx < 256; idx += 512)
      out[batch*256 + idx] = y_s[((idx & 63) << 2) + (idx >> 6)];
  } else {
    if (tid < 128 && (tid & 7) == 0) ls16[tid >> 3] = lsacc;
    __syncthreads();
    if (tid == 0 && out_n >= 8224){
      float s = 0.f;
      #pragma unroll
      for (int w = 0; w < 16; w++) s += ls16[w];
      out[8192 + batch] = s;
    }
  }

  asm volatile("barrier.cluster.arrive.aligned;" ::: "memory");
  asm volatile("barrier.cluster.wait.aligned;"   ::: "memory");
}

extern "C" void kernel_launch(void* const* d_in, const int* in_sizes, int n_in,
                              void* d_out, int out_size) {
  const float* p[17];
  for (int i = 0; i < 17 && i < n_in; i++) p[i] = (const float*)d_in[i];
  made_flow_kernel<<<64, 512>>>(
    p[0],
    p[1], p[2], p[3], p[4], p[5], p[6], p[7], p[8],
    p[9], p[10], p[11], p[12], p[13], p[14], p[15], p[16],
    (float*)d_out, out_size);
}

// round 15
// speedup vs baseline: 1.4326x; 1.0204x over previous
#include <cuda_runtime.h>
#include <cstdint>

// AF2dMADEBlock: wavefront-parallel raster sweep (t = x + 2y, 22 steps).
// Cluster of 2 CTAs per batch (rank0=mu, rank1=lv), 512 thr/CTA.
// R15: SINGLE-WAITER exchange — only warp 0 polls the mbarrier (recv data is
// consumed only by its first 16 lanes for y), eliminating multi-warp TRYWAIT
// contention and wake spread. Conv+send on warps 4-7. Otherwise R14.

#define EPS 1e-12f
#define H1OFF (67*64)      // layer-1 offset inside hg (floats)
typedef unsigned long long ull;

__device__ __forceinline__ uint32_t smem_u32(const void* p){
  return (uint32_t)__cvta_generic_to_shared((void*)p);
}
__device__ __forceinline__ float elu_f(float x){
  return x > 0.f ? x : (__expf(x) - 1.f);
}
__device__ __forceinline__ void fma2(ull& acc, ull a, ull b){
  asm("fma.rn.f32x2 %0, %1, %2, %0;" : "+l"(acc) : "l"(a), "l"(b));
}
__device__ __forceinline__ ull pack2(float lo, float hi){
  ull r; asm("mov.b64 %0, {%1, %2};" : "=l"(r) : "f"(lo), "f"(hi)); return r;
}
__device__ __forceinline__ float hsum1(ull a){
  float x, y;
  asm("mov.b64 {%0, %1}, %2;" : "=f"(x), "=f"(y) : "l"(a));
  return x + y;
}
// wavefront w: pixels (y, x=w-2y), y in [ymin, ymax]
__device__ __forceinline__ void wf(int w, int& ymin, int& n){
  ymin = (w <= 7) ? 0 : ((w - 6) >> 1);
  int ymax = w >> 1; if (ymax > 7) ymax = 7;
  n = ymax - ymin + 1;
  if (n < 0) n = 0;
}

__global__ void __cluster_dims__(2,1,1) __launch_bounds__(512,1)
made_flow_kernel(const float* __restrict__ xg,
  const float* __restrict__ mw0, const float* __restrict__ mb0,
  const float* __restrict__ mw1, const float* __restrict__ mb1,
  const float* __restrict__ mw2, const float* __restrict__ mb2,
  const float* __restrict__ mwo, const float* __restrict__ mbo,
  const float* __restrict__ lw0, const float* __restrict__ lb0,
  const float* __restrict__ lw1, const float* __restrict__ lb1,
  const float* __restrict__ lw2, const float* __restrict__ lb2,
  const float* __restrict__ lwo, const float* __restrict__ lbo,
  float* __restrict__ out, int out_n)
{
  // hg[layer][row][ch]: rows 0..63 pixels, 64 = permanent zero, 65 = scratch
  __shared__ __align__(16) float hg[2*67*64];
  __shared__ __align__(16) float w0s[16*64];    // mask-A w0: [(tap*4+ic)][o]
  __shared__ __align__(16) float y_s[65*4];     // row 64 = zero
  __shared__ __align__(16) float x_s[64*4];
  __shared__ __align__(16) float h2s[4*68];     // [slot][ch], stride 68
  __shared__ float b0s[64], b1s[64], b2s[64];
  __shared__ __align__(16) float wos[4*68];     // [oc][c], stride 68
  __shared__ float bos[4];
  __shared__ __align__(16) float recv[2][2][16]; // [net][par][slot*4+oc]
  __shared__ float ls16[16];
  __shared__ __align__(8) unsigned long long mbar[2];
  __shared__ uchar4 pixT[23];                   // pixel id per (step, slot); 65=invalid
  __shared__ uchar4 tapT[23][4];                // tap ids per (wave, slot); 64=OOB
  __shared__ unsigned char nT[24];

  const int tid = threadIdx.x;
  uint32_t rank; asm("mov.u32 %0, %%cluster_ctarank;" : "=r"(rank));
  const int batch = blockIdx.x >> 1;

  const float* w0g = rank ? lw0 : mw0;
  const float* b0g = rank ? lb0 : mb0;
  const float* w1g = rank ? lw1 : mw1;
  const float* b1g = rank ? lb1 : mb1;
  const float* w2g = rank ? lw2 : mw2;
  const float* b2g = rank ? lb2 : mb2;
  const float* wog = rank ? lwo : mwo;
  const float* bog = rank ? lbo : mbo;

  if (tid == 0){
    asm volatile("mbarrier.init.shared.b64 [%0], %1;"
                 :: "r"(smem_u32(&mbar[0])), "r"(1u) : "memory");
    asm volatile("mbarrier.init.shared.b64 [%0], %1;"
                 :: "r"(smem_u32(&mbar[1])), "r"(1u) : "memory");
    asm volatile("mbarrier.arrive.expect_tx.shared.b64 _, [%0], %1;"
                 :: "r"(smem_u32(&mbar[0])), "r"(32u) : "memory");
    asm volatile("mbarrier.arrive.expect_tx.shared.b64 _, [%0], %1;"
                 :: "r"(smem_u32(&mbar[1])), "r"(32u) : "memory");
  }

  // ---- Wavefront tables ----
  if (tid < 92){
    int w = tid >> 2, k = tid & 3;
    int ymin, n; wf(w, ymin, n);
    if (k == 0) nT[w] = (unsigned char)n;
    unsigned char pix = 65, tq[4] = {64,64,64,64};
    if (k < n){
      int y = ymin + k, x = w - 2*y;
      pix = (unsigned char)(y*8 + x);
      #pragma unroll
      for (int tt = 0; tt < 3; tt++){
        int qy = y - 1, qx = x - 1 + tt;
        tq[tt] = (qy >= 0 && qx >= 0 && qx < 8) ? (unsigned char)(qy*8 + qx) : 64;
      }
      tq[3] = (x > 0) ? (unsigned char)(pix - 1) : 64;
    }
    ((unsigned char*)&pixT[w])[k] = pix;
    tapT[w][k] = make_uchar4(tq[0], tq[1], tq[2], tq[3]);
  }
  if (tid == 92) nT[23] = 0;

  // ---- Stage small weights/biases/x; zero rows ----
  for (int idx = tid; idx < 1024; idx += 512){
    int r = idx >> 6, oo = idx & 63;
    int t = r >> 2, ic = r & 3;
    int ky = (t == 3) ? 1 : 0;
    int kx = (t == 3) ? 0 : t;
    w0s[idx] = w0g[(oo*4 + ic)*9 + ky*3 + kx];
  }
  if (tid < 64){
    float bv = b0g[tid];
    b0s[tid] = bv; b1s[tid] = b1g[tid]; b2s[tid] = b2g[tid];
    hg[tid] = elu_f(bv);                 // h0[pixel 0]
    hg[64*64 + tid] = 0.f;               // zero rows
    hg[H1OFF + 64*64 + tid] = 0.f;
  }
  if (tid < 256) wos[(tid >> 6)*68 + (tid & 63)] = wog[tid];
  if (tid < 4){  bos[tid] = bog[tid]; y_s[256 + tid] = 0.f; }
  if (tid < 16)  ls16[tid] = 0.f;
  if (tid < 256){
    int pos = tid & 63, c = tid >> 6;
    x_s[pos*4 + c] = xg[batch*256 + tid];
  }

  // ---- Masked mask-B weights, packed f32x2 ----
  const int o = tid >> 3;
  const int j = tid & 7;
  ull w1p[20], w2p[20];
  #pragma unroll
  for (int i = 0; i < 10; i++){
    float t1[4], t2[4];
    #pragma unroll
    for (int m = 0; m < 4; m++){
      int k  = (j << 2) + (i << 5) + m;
      int t  = k >> 6, ic = k & 63;
      int ky = (t >= 3) ? 1 : 0;
      int kx = (t >= 3) ? (t - 3) : t;
      int gi = (o*64 + ic)*9 + ky*3 + kx;
      t1[m] = w1g[gi];
      t2[m] = w2g[gi];
    }
    w1p[2*i]   = pack2(t1[0], t1[1]);
    w1p[2*i+1] = pack2(t1[2], t1[3]);
    w2p[2*i]   = pack2(t2[0], t2[1]);
    w2p[2*i+1] = pack2(t2[2], t2[3]);
  }

  __syncthreads();
  asm volatile("barrier.cluster.arrive.aligned;" ::: "memory");
  asm volatile("barrier.cluster.wait.aligned;"   ::: "memory");

  float lsacc = 0.f;
  ull pA[4] = {0,0,0,0}, pB[4] = {0,0,0,0};
  float h0up = 0.f;                      // hoisted h0 partial (taps 0-1 only)
  const int joff = j << 2;

  for (int t = 0; t < 22; t++){
    const int n  = nT[t];
    const int n1 = nT[t+1];
    const uchar4 pxv = pixT[t];
    const int pls[4] = {pxv.x, pxv.y, pxv.z, pxv.w};

    // ---- Phase A: h1 for wave-t pixels ----
    {
      float s[4];
      #pragma unroll
      for (int k = 0; k < 4; k++){
        if (k < n){
          const float* cb = &hg[pls[k]*64 + joff];
          ulonglong2 c0 = *(const ulonglong2*)cb;
          ulonglong2 c1 = *(const ulonglong2*)(cb + 32);
          ull a = pA[k];
          fma2(a, w1p[16], c0.x); fma2(a, w1p[17], c0.y);
          fma2(a, w1p[18], c1.x); fma2(a, w1p[19], c1.y);
          s[k] = hsum1(a);
        } else s[k] = 0.f;
      }
      #pragma unroll
      for (int k = 0; k < 4; k++) s[k] += __shfl_xor_sync(0xffffffffu, s[k], 4, 8);
      #pragma unroll
      for (int k = 0; k < 4; k++) s[k] += __shfl_xor_sync(0xffffffffu, s[k], 2, 8);
      #pragma unroll
      for (int k = 0; k < 4; k++) s[k] += __shfl_xor_sync(0xffffffffu, s[k], 1, 8);
      if (j == 0){
        #pragma unroll
        for (int k = 0; k < 4; k++)
          if (k < n) hg[H1OFF + pls[k]*64 + o] = elu_f(b1s[o] + s[k]);
      }
    }
    __syncthreads();

    // ---- Phase B: h2 for wave-t pixels ----
    {
      float s[4];
      #pragma unroll
      for (int k = 0; k < 4; k++){
        if (k < n){
          const float* cb = &hg[H1OFF + pls[k]*64 + joff];
          ulonglong2 c0 = *(const ulonglong2*)cb;
          ulonglong2 c1 = *(const ulonglong2*)(cb + 32);
          ull a = pB[k];
          fma2(a, w2p[16], c0.x); fma2(a, w2p[17], c0.y);
          fma2(a, w2p[18], c1.x); fma2(a, w2p[19], c1.y);
          s[k] = hsum1(a);
        } else s[k] = 0.f;
      }
      #pragma unroll
      for (int k = 0; k < 4; k++) s[k] += __shfl_xor_sync(0xffffffffu, s[k], 4, 8);
      #pragma unroll
      for (int k = 0; k < 4; k++) s[k] += __shfl_xor_sync(0xffffffffu, s[k], 2, 8);
      #pragma unroll
      for (int k = 0; k < 4; k++) s[k] += __shfl_xor_sync(0xffffffffu, s[k], 1, 8);
      if (j == 0){
        #pragma unroll
        for (int k = 0; k < 4; k++)
          if (k < n) h2s[k*68 + o] = elu_f(b2s[o] + s[k]);
      }
    }
    __syncthreads();

    // ---- Phase C ----
    const int par = t & 1;
    const uint32_t parity = (uint32_t)((t >> 1) & 1);

    // conv + send: warps 4-7 (tid 128..255); slot kp = warp-4, 8-lane groups = oc
    if (tid >= 128 && tid < 256){
      const int kp = (tid >> 5) - 4;
      const int oc = (tid >> 3) & 3;
      const int j8 = tid & 7;
      if (kp < n){
        const ulonglong2* hp = (const ulonglong2*)&h2s[kp*68 + j8*8];
        const ulonglong2* wp = (const ulonglong2*)&wos[oc*68 + j8*8];
        ulonglong2 hv0 = hp[0], hv1 = hp[1];
        ulonglong2 wv0 = wp[0], wv1 = wp[1];
        ull a0 = 0ull, a1 = 0ull;
        fma2(a0, wv0.x, hv0.x); fma2(a1, wv0.y, hv0.y);
        fma2(a0, wv1.x, hv1.x); fma2(a1, wv1.y, hv1.y);
        float pr = hsum1(a0) + hsum1(a1);
        pr += __shfl_xor_sync(0xffffffffu, pr, 4, 8);
        pr += __shfl_xor_sync(0xffffffffu, pr, 2, 8);
        pr += __shfl_xor_sync(0xffffffffu, pr, 1, 8);
        if (j8 == 0){
          float v = bos[oc] + pr;
          if (rank){ v *= 0.5f; lsacc += v; }
          uint32_t val = __float_as_uint(v);
          uint32_t lrec = smem_u32(&recv[rank][par][(kp << 2) + oc]);
          uint32_t lbar = smem_u32(&mbar[par]);
          uint32_t d0, b0a, d1, b1a;
          asm volatile("mapa.shared::cluster.u32 %0, %1, %2;" : "=r"(d0)  : "r"(lrec), "r"(0u));
          asm volatile("mapa.shared::cluster.u32 %0, %1, %2;" : "=r"(b0a) : "r"(lbar), "r"(0u));
          asm volatile("mapa.shared::cluster.u32 %0, %1, %2;" : "=r"(d1)  : "r"(lrec), "r"(1u));
          asm volatile("mapa.shared::cluster.u32 %0, %1, %2;" : "=r"(b1a) : "r"(lbar), "r"(1u));
          asm volatile("st.async.shared::cluster.mbarrier::complete_tx::bytes.u32 [%0], %1, [%2];"
                       :: "r"(d0), "r"(val), "r"(b0a) : "memory");
          asm volatile("st.async.shared::cluster.mbarrier::complete_tx::bytes.u32 [%0], %1, [%2];"
                       :: "r"(d1), "r"(val), "r"(b1a) : "memory");
        }
      }
    }

    // past-tap partials for wave t+1 (both layers), table-driven — all threads
    #pragma unroll
    for (int k = 0; k < 4; k++){
      if (k < n1){
        const uchar4 tq = tapT[t+1][k];
        const int taps[4] = {tq.x, tq.y, tq.z, tq.w};
        ull A = 0ull, B = 0ull;
        #pragma unroll
        for (int m = 0; m < 4; m++){
          const float* bp = &hg[taps[m]*64 + joff];
          ulonglong2 u0 = *(const ulonglong2*)bp;
          ulonglong2 u1 = *(const ulonglong2*)(bp + 32);
          ulonglong2 v0 = *(const ulonglong2*)(bp + H1OFF);
          ulonglong2 v1 = *(const ulonglong2*)(bp + H1OFF + 32);
          fma2(A, w1p[4*m],   u0.x); fma2(A, w1p[4*m+1], u0.y);
          fma2(A, w1p[4*m+2], u1.x); fma2(A, w1p[4*m+3], u1.y);
          fma2(B, w2p[4*m],   v0.x); fma2(B, w2p[4*m+1], v0.y);
          fma2(B, w2p[4*m+2], v1.x); fma2(B, w2p[4*m+3], v1.y);
        }
        pA[k] = A; pB[k] = B;
      }
    }

    if (tid < 256){
      // h0 partial for wave t+1: taps 0 (wave t-2) and 1 (wave t-1) are final
      {
        const int kp = tid >> 6, ch = tid & 63;
        const uchar4 tq = tapT[t+1][kp];
        float acc = b0s[ch];
        float4 yq0 = *(const float4*)&y_s[tq.x << 2];
        float4 yq1 = *(const float4*)&y_s[tq.y << 2];
        acc = fmaf(w0s[0*64 + ch], yq0.x, acc);
        acc = fmaf(w0s[1*64 + ch], yq0.y, acc);
        acc = fmaf(w0s[2*64 + ch], yq0.z, acc);
        acc = fmaf(w0s[3*64 + ch], yq0.w, acc);
        acc = fmaf(w0s[4*64 + ch], yq1.x, acc);
        acc = fmaf(w0s[5*64 + ch], yq1.y, acc);
        acc = fmaf(w0s[6*64 + ch], yq1.z, acc);
        acc = fmaf(w0s[7*64 + ch], yq1.w, acc);
        h0up = acc;
      }

      // SINGLE-WAITER: only warp 0 polls the mbarrier and computes y
      if (tid < 32){
        uint32_t lbar = smem_u32(&mbar[par]);
        uint32_t done;
        do {
          asm volatile("{\n\t.reg .pred p;\n\t"
            "mbarrier.try_wait.parity.acquire.cta.shared::cta.b64 p, [%1], %2, 0x989680;\n\t"
            "selp.b32 %0, 1, 0, p;\n\t}"
            : "=r"(done) : "r"(lbar), "r"(parity) : "memory");
        } while (!done);
        if (tid == 0 && t + 2 < 22){
          asm volatile("mbarrier.arrive.expect_tx.shared.b64 _, [%0], %1;"
                       :: "r"(lbar), "r"((uint32_t)(32*nT[t+2])) : "memory");
        }
        if (tid < 16){
          const int kp = tid >> 2, c = tid & 3;
          if (kp < n){
            const int p = pls[kp];
            float mu = recv[0][par][(kp << 2) + c];
            float lv = recv[1][par][(kp << 2) + c];
            y_s[(p << 2) + c] = __fdividef(x_s[(p << 2) + c] - mu, __expf(lv) + EPS);
          }
        }
      }
      asm volatile("bar.sync 1, 256;" ::: "memory");
      // h0 tail: taps 2 (up-right, wave t) and 3 (left, wave t) + ELU + store
      {
        const int kp = tid >> 6, ch = tid & 63;
        const uchar4 tq = tapT[t+1][kp];
        const int wp = ((const unsigned char*)&pixT[t+1])[kp];
        float acc = h0up;
        float4 y2 = *(const float4*)&y_s[tq.z << 2];
        float4 y3 = *(const float4*)&y_s[tq.w << 2];
        acc = fmaf(w0s[ 8*64 + ch], y2.x, acc);
        acc = fmaf(w0s[ 9*64 + ch], y2.y, acc);
        acc = fmaf(w0s[10*64 + ch], y2.z, acc);
        acc = fmaf(w0s[11*64 + ch], y2.w, acc);
        acc = fmaf(w0s[12*64 + ch], y3.x, acc);
        acc = fmaf(w0s[13*64 + ch], y3.y, acc);
        acc = fmaf(w0s[14*64 + ch], y3.z, acc);
        acc = fmaf(w0s[15*64 + ch], y3.w, acc);
        hg[wp*64 + ch] = elu_f(acc);
      }
    }
    __syncthreads();
  }

  // ---- Outputs ----
  if (rank == 0){
    for (int idx = tid; idx < 256; idx += 512)
      out[batch*256 + idx] = y_s[((idx & 63) << 2) + (idx >> 6)];
  } else {
    if (tid >= 128 && tid < 256 && (tid & 7) == 0) ls16[(tid - 128) >> 3] = lsacc;
    __syncthreads();
    if (tid == 0 && out_n >= 8224){
      float s = 0.f;
      #pragma unroll
      for (int w = 0; w < 16; w++) s += ls16[w];
      out[8192 + batch] = s;
    }
  }

  asm volatile("barrier.cluster.arrive.aligned;" ::: "memory");
  asm volatile("barrier.cluster.wait.aligned;"   ::: "memory");
}

extern "C" void kernel_launch(void* const* d_in, const int* in_sizes, int n_in,
                              void* d_out, int out_size) {
  const float* p[17];
  for (int i = 0; i < 17 && i < n_in; i++) p[i] = (const float*)d_in[i];
  made_flow_kernel<<<64, 512>>>(
    p[0],
    p[1], p[2], p[3], p[4], p[5], p[6], p[7], p[8],
    p[9], p[10], p[11], p[12], p[13], p[14], p[15], p[16],
    (float*)d_out, out_size);
}